// round 4
// baseline (speedup 1.0000x reference)
#include <cuda_runtime.h>
#include <math.h>
#include <stdint.h>

// ---------------- problem constants ----------------
#define BB   16
#define TT   2048
#define LL   512
#define HH   256
#define HH2  512
#define CVQd 64
#define NLB  10   // NL * NB

// ---------------- scratch ----------------
#define SZ_BHT  ((size_t)BB*HH*TT)
#define SZ_BMT  ((size_t)BB*HH2*TT)
#define SZ_SEG  ((size_t)BB*HH*(LL+1))
#define SZ_CNT  ((size_t)BB*(LL+1))
#define SZ_BZL  ((size_t)BB*CVQd*LL)
__device__ __align__(16) float g_scratch[3*SZ_BHT + SZ_BMT + SZ_SEG + SZ_CNT + 2*SZ_BZL + 64];

// ---------------- helpers ----------------
__device__ __forceinline__ float tf32_rna(float x) {
    uint32_t u;
    asm("cvt.rna.tf32.f32 %0, %1;" : "=r"(u) : "f"(x));
    return __uint_as_float(u);
}

#define MMA_TF32(C, A, B)                                                        \
    asm volatile("mma.sync.aligned.m16n8k8.row.col.f32.tf32.tf32.f32 "           \
        "{%0,%1,%2,%3}, {%4,%5,%6,%7}, {%8,%9}, {%0,%1,%2,%3};"                  \
        : "+f"((C)[0]), "+f"((C)[1]), "+f"((C)[2]), "+f"((C)[3])                  \
        : "r"((A)[0]), "r"((A)[1]), "r"((A)[2]), "r"((A)[3]),                     \
          "r"((B)[0]), "r"((B)[1]))

// ---------------- per-(b,t) LayerNorm stats: mean + rstd ----------------
__global__ void ln_stats(const float* __restrict__ in, float2* __restrict__ stats, int Tdim)
{
    int idx = blockIdx.x * blockDim.x + threadIdx.x;
    if (idx >= BB * Tdim) return;
    int b = idx / Tdim, t = idx - b * Tdim;
    const float* p = in + (size_t)b * HH * Tdim + t;
    float s = 0.f, s2 = 0.f;
    #pragma unroll 8
    for (int c = 0; c < HH; c++) { float v = p[(size_t)c * Tdim]; s += v; s2 += v * v; }
    float mean = s * (1.f / HH);
    float var  = s2 * (1.f / HH) - mean * mean;
    stats[idx] = make_float2(mean, rsqrtf(var + 1e-5f));
}

// ---------------- 3xTF32 tensor-core conv GEMM (fragment-ordered smem) ----------------
// out[b,co,t] = sum_{ci,tap} w[co,ci,tap] * LN?(in[b,ci,t+tap-(KS-1)])
// BM=64 (Cout) x BN=128 (T), BK=16, 256 threads = 8 warps (2M x 4N), double-buffered.
template<int KS>
__global__ void __launch_bounds__(256, 2)
mma_conv(const float* __restrict__ in, const float* __restrict__ w,
         const float* __restrict__ bias, float* out,
         const float* residual, const float* __restrict__ mask,
         const float2* __restrict__ lnstats, const float* __restrict__ lng,
         const float* __restrict__ lnb, const float* __restrict__ lnmask,
         int Cin, int Cout, int Tdim, float scale, int dogelu)
{
    // A: [buf2][k8b2][m16b4][64 f4 slots]   B: [buf2][k8b2][n8b16][32 f4 slots]
    __shared__ float4 Af4[1024];
    __shared__ float4 Bf4[2048];

    const int b   = blockIdx.z;
    const int cog = blockIdx.y * 64;
    const int tg  = blockIdx.x * 128;
    const int tid = threadIdx.x;
    const int lane = tid & 31;
    const int wid = tid >> 5;
    const int wm = wid >> 2, wn = wid & 3;

    const float* inB = in + (size_t)b * Cin * Tdim;
    const int nk = (Cin * KS) >> 4;
    const bool doln = (lnstats != nullptr);

    // ---- loader constants ----
    // B loader: thread handles column n_col, 4 (k8b,th) groups, 2 k-rows each
    const int n_col = tid & 127;
    const int tsel  = tid >> 7;
    const int b_n8b = n_col >> 3;
    // A loader: 2 groups (k8b = i), fixed (m16b, khalf, lane)
    const int a_m16b = (tid >> 6) & 3;
    const int a_h4   = ((tid >> 5) & 1) * 4;
    const int a_lane = tid & 31;
    const int a_ga   = a_lane >> 2, a_th = a_lane & 3;
    const int a_s    = 2 * a_lane + ((tid >> 5) & 1);
    const int a_slot = a_s ^ (a_s >> 3);

    int b_slot[4], b_k8[4], b_row[4];
    #pragma unroll
    for (int i = 0; i < 4; i++) {
        int sel = 2 * i + tsel;
        int th = sel & 3;
        b_k8[i] = sel >> 2;
        b_row[i] = b_k8[i] * 8 + th;
        int lb = ((n_col & 7) << 2) | th;
        b_slot[i] = lb ^ (lb >> 2);
    }

    // reader constants
    const int r_slotB = lane ^ (lane >> 2);
    const int r_sa0 = (2 * lane) ^ (lane >> 2);
    const int r_sa1 = (2 * lane + 1) ^ (lane >> 2);

    float c[2][4][4];
    #pragma unroll
    for (int i = 0; i < 2; i++)
        #pragma unroll
        for (int j = 0; j < 4; j++)
            #pragma unroll
            for (int k = 0; k < 4; k++) c[i][j][k] = 0.f;

    float av[4], bv[8];

    // ---------- prefetch chunk kc into registers ----------
    auto prefetch = [&](int kc) {
        int kk = kc << 4;
        int tap = (KS == 1) ? 0 : (kk / Cin);
        int ci0 = kk - tap * Cin;
        int tshift = tap - (KS - 1);
        // A: weights
        #pragma unroll
        for (int i = 0; i < 2; i++) {
            int k = i * 8 + a_h4 + a_th;
            size_t base = ((size_t)(cog + a_m16b * 16 + a_ga) * Cin + ci0 + k) * KS + tap;
            av[i * 2 + 0] = w[base];
            av[i * 2 + 1] = w[base + (size_t)8 * Cin * KS];
        }
        // B: activations (optionally LayerNormed)
        int t = tg + n_col + tshift;
        float2 st = make_float2(0.f, 0.f);
        float mk = 1.f;
        if (t >= 0) {
            if (doln) st = lnstats[b * Tdim + t];
            if (lnmask) mk = lnmask[b * Tdim + t];
        }
        #pragma unroll
        for (int i = 0; i < 4; i++) {
            #pragma unroll
            for (int j = 0; j < 2; j++) {
                int ci = ci0 + b_row[i] + j * 4;
                float v = 0.f;
                if (t >= 0) {
                    v = inB[(size_t)ci * Tdim + t];
                    if (doln) v = (v - st.x) * st.y * lng[ci] + lnb[ci];
                    if (lnmask) v *= mk;
                }
                bv[i * 2 + j] = v;
            }
        }
    };

    // ---------- convert + store prefetched regs into smem buffer ----------
    auto commit = [&](int buf) {
        #pragma unroll
        for (int i = 0; i < 2; i++) {
            float h0 = tf32_rna(av[i * 2 + 0]);
            float l0 = tf32_rna(av[i * 2 + 0] - h0);
            float h1 = tf32_rna(av[i * 2 + 1]);
            float l1 = tf32_rna(av[i * 2 + 1] - h1);
            Af4[buf * 512 + i * 256 + a_m16b * 64 + a_slot] = make_float4(h0, l0, h1, l1);
        }
        #pragma unroll
        for (int i = 0; i < 4; i++) {
            float h0 = tf32_rna(bv[i * 2 + 0]);
            float l0 = tf32_rna(bv[i * 2 + 0] - h0);
            float h1 = tf32_rna(bv[i * 2 + 1]);
            float l1 = tf32_rna(bv[i * 2 + 1] - h1);
            Bf4[buf * 1024 + b_k8[i] * 512 + b_n8b * 32 + b_slot[i]] = make_float4(h0, l0, h1, l1);
        }
    };

    prefetch(0);
    commit(0);
    __syncthreads();

    for (int kc = 0; kc < nk; kc++) {
        int buf = kc & 1;
        if (kc + 1 < nk) prefetch(kc + 1);

        #pragma unroll
        for (int k8b = 0; k8b < 2; k8b++) {
            float4 aq[2][2];
            #pragma unroll
            for (int mf = 0; mf < 2; mf++) {
                const float4* pa = Af4 + buf * 512 + k8b * 256 + (wm * 2 + mf) * 64;
                aq[mf][0] = pa[r_sa0];
                aq[mf][1] = pa[r_sa1];
            }
            float4 bq[4];
            #pragma unroll
            for (int nf = 0; nf < 4; nf++)
                bq[nf] = Bf4[buf * 1024 + k8b * 512 + (wn * 4 + nf) * 32 + r_slotB];

            #pragma unroll
            for (int mf = 0; mf < 2; mf++) {
                uint32_t ah[4] = { __float_as_uint(aq[mf][0].x), __float_as_uint(aq[mf][0].z),
                                   __float_as_uint(aq[mf][1].x), __float_as_uint(aq[mf][1].z) };
                uint32_t al[4] = { __float_as_uint(aq[mf][0].y), __float_as_uint(aq[mf][0].w),
                                   __float_as_uint(aq[mf][1].y), __float_as_uint(aq[mf][1].w) };
                #pragma unroll
                for (int nf = 0; nf < 4; nf++) {
                    uint32_t bh[2] = { __float_as_uint(bq[nf].x), __float_as_uint(bq[nf].z) };
                    uint32_t bl[2] = { __float_as_uint(bq[nf].y), __float_as_uint(bq[nf].w) };
                    MMA_TF32(c[mf][nf], ah, bh);
                    MMA_TF32(c[mf][nf], ah, bl);
                    MMA_TF32(c[mf][nf], al, bh);
                }
            }
        }
        if (kc + 1 < nk) commit(buf ^ 1);
        __syncthreads();
    }

    // ---- epilogue ----
    const int g = lane >> 2, th = lane & 3;
    #pragma unroll
    for (int mf = 0; mf < 2; mf++) {
        int m0 = cog + wm * 32 + mf * 16 + g;
        float bi0 = bias[m0], bi1 = bias[m0 + 8];
        #pragma unroll
        for (int nf = 0; nf < 4; nf++) {
            int t0 = tg + wn * 32 + nf * 8 + 2 * th;
            #pragma unroll
            for (int half = 0; half < 2; half++) {
                int m = half ? m0 + 8 : m0;
                float bi = half ? bi1 : bi0;
                float v0 = (c[mf][nf][half * 2 + 0] + bi) * scale;
                float v1 = (c[mf][nf][half * 2 + 1] + bi) * scale;
                if (dogelu) {
                    v0 = 0.5f * v0 * (1.f + erff(v0 * 0.70710678118654752f));
                    v1 = 0.5f * v1 * (1.f + erff(v1 * 0.70710678118654752f));
                }
                size_t oi = ((size_t)b * Cout + m) * Tdim + t0;
                if (residual) { v0 += residual[oi]; v1 += residual[oi + 1]; }
                if (mask) {
                    v0 *= mask[b * Tdim + t0];
                    v1 *= mask[b * Tdim + t0 + 1];
                }
                out[oi] = v0; out[oi + 1] = v1;
            }
        }
    }
}

// ---------------- group_by_segs ----------------
__global__ void seg_zero(float* seg, float* cnt)
{
    int i = blockIdx.x * blockDim.x + threadIdx.x;
    if (i < (int)SZ_SEG) seg[i] = 0.f;
    if (i < (int)SZ_CNT) cnt[i] = 0.f;
}
__global__ void seg_scatter(const float* __restrict__ in, const int* __restrict__ mel2ph,
                            float* seg, float* cnt)
{
    int t = blockIdx.x, b = blockIdx.y, c = threadIdx.x;
    int ph = mel2ph[b * TT + t];
    if (ph < 1 || ph > LL) return;
    float v = in[((size_t)b * HH + c) * TT + t];
    atomicAdd(&seg[((size_t)b * HH + c) * (LL + 1) + ph], v);
    if (c == 0) atomicAdd(&cnt[b * (LL + 1) + ph], 1.f);
}
__global__ void seg_div(const float* __restrict__ seg, const float* __restrict__ cnt,
                        float* __restrict__ outg)
{
    int i = blockIdx.x * blockDim.x + threadIdx.x;
    if (i >= BB * HH * LL) return;
    int l = i % LL; int bc = i / LL; int c = bc % HH; int b = bc / HH;
    float s = seg[((size_t)b * HH + c) * (LL + 1) + l + 1];
    float n = fmaxf(cnt[b * (LL + 1) + l + 1], 1.f);
    outg[i] = s / n;
}

// ---------------- VQ ----------------
__global__ void loss_init(float* loss) { if (threadIdx.x == 0) *loss = 0.f; }

__global__ void vq_kernel(const float* __restrict__ z, const float* __restrict__ cb,
                          float* __restrict__ q, float* __restrict__ outIdx, float* loss)
{
    __shared__ float zsh[64];
    __shared__ float dsh[128];
    __shared__ int   ish[128];
    int l = blockIdx.x, b = blockIdx.y, tid = threadIdx.x;
    if (tid < 64) zsh[tid] = z[((size_t)b * CVQd + tid) * LL + l];
    __syncthreads();
    float x2 = 0.f, dot = 0.f, c2 = 0.f;
    #pragma unroll 8
    for (int c = 0; c < 64; c++) {
        float zv = zsh[c]; float cv = cb[tid * 64 + c];
        x2 += zv * zv; dot += zv * cv; c2 += cv * cv;
    }
    dsh[tid] = x2 - 2.f * dot + c2;
    ish[tid] = tid;
    __syncthreads();
    for (int s = 64; s > 0; s >>= 1) {
        if (tid < s) {
            float d2 = dsh[tid + s]; int i2 = ish[tid + s];
            if (d2 < dsh[tid] || (d2 == dsh[tid] && i2 < ish[tid])) { dsh[tid] = d2; ish[tid] = i2; }
        }
        __syncthreads();
    }
    int best = ish[0];
    __syncthreads();
    float part = 0.f;
    if (tid < 64) {
        float qv = cb[best * 64 + tid];
        q[((size_t)b * CVQd + tid) * LL + l] = qv;
        float dd = zsh[tid] - qv;
        part = dd * dd;
    }
    dsh[tid] = part;
    __syncthreads();
    for (int s = 64; s > 0; s >>= 1) { if (tid < s) dsh[tid] += dsh[tid + s]; __syncthreads(); }
    if (tid == 0) {
        atomicAdd(loss, dsh[0]);
        outIdx[b * LL + l] = (float)best;
    }
}

__global__ void loss_fin(const float* loss, float* out)
{
    out[0] = loss[0] * 0.25f / (float)(BB * LL * CVQd);
}

// ---------------- launch ----------------
extern "C" void kernel_launch(void* const* d_in, const int* in_sizes, int n_in,
                              void* d_out, int out_size)
{
    float* scratch = nullptr;
    cudaGetSymbolAddress((void**)&scratch, g_scratch);
    float* bx  = scratch;
    float* bn  = bx + SZ_BHT;          // LN stats (float2) live here
    float* by  = bn + SZ_BHT;
    float* bm  = by + SZ_BHT;
    float* seg = bm + SZ_BMT;
    float* cnt = seg + SZ_SEG;
    float* bz  = cnt + SZ_CNT;
    float* bq  = bz + SZ_BZL;
    float* loss = bq + SZ_BZL;
    float2* stats = (float2*)bn;

    const float* x        = (const float*)d_in[0];
    const float* in_mask  = (const float*)d_in[1];
    const int*   mel2ph   = (const int*)  d_in[2];
    const float* ph_mask  = (const float*)d_in[3];
    const float* conv_in_w = (const float*)d_in[4];
    const float* conv_in_b = (const float*)d_in[5];
    const float* enc_ln_g = (const float*)d_in[6];
    const float* enc_ln_b = (const float*)d_in[7];
    const float* enc_w1   = (const float*)d_in[8];
    const float* enc_b1   = (const float*)d_in[9];
    const float* enc_w2   = (const float*)d_in[10];
    const float* enc_b2   = (const float*)d_in[11];
    const float* enc_last_g = (const float*)d_in[12];
    const float* enc_last_b = (const float*)d_in[13];
    const float* enc_post_w = (const float*)d_in[14];
    const float* enc_post_b = (const float*)d_in[15];
    const float* pn_ln_g = (const float*)d_in[16];
    const float* pn_ln_b = (const float*)d_in[17];
    const float* pn_w1   = (const float*)d_in[18];
    const float* pn_b1   = (const float*)d_in[19];
    const float* pn_w2   = (const float*)d_in[20];
    const float* pn_b2   = (const float*)d_in[21];
    const float* pn_last_g = (const float*)d_in[22];
    const float* pn_last_b = (const float*)d_in[23];
    const float* pn_post_w = (const float*)d_in[24];
    const float* pn_post_b = (const float*)d_in[25];
    const float* proj_in_w  = (const float*)d_in[26];
    const float* proj_in_b  = (const float*)d_in[27];
    const float* proj_out_w = (const float*)d_in[28];
    const float* proj_out_b = (const float*)d_in[29];
    const float* codebook   = (const float*)d_in[30];

    float* out = (float*)d_out;
    const float scale = 0.57735026918962576f;   // 3^-0.5
    dim3 blk(256);

    // ---- encoder (T = TT) ----
    mma_conv<1><<<dim3(TT/128, HH/64, BB), blk>>>(x, conv_in_w, conv_in_b, bx,
        nullptr, in_mask, nullptr, nullptr, nullptr, nullptr, 80, HH, TT, 1.f, 0);
    for (int i = 0; i < NLB; i++) {
        ln_stats<<<(BB*TT + 255)/256, 256>>>(bx, stats, TT);
        mma_conv<3><<<dim3(TT/128, HH2/64, BB), blk>>>(bx, enc_w1 + (size_t)i*HH2*HH*3,
            enc_b1 + i*HH2, bm, nullptr, nullptr,
            stats, enc_ln_g + i*HH, enc_ln_b + i*HH, nullptr, HH, HH2, TT, scale, 1);
        mma_conv<1><<<dim3(TT/128, HH/64, BB), blk>>>(bm, enc_w2 + (size_t)i*HH*HH2,
            enc_b2 + i*HH, bx, bx, in_mask,
            nullptr, nullptr, nullptr, nullptr, HH2, HH, TT, 1.f, 0);
    }
    ln_stats<<<(BB*TT + 255)/256, 256>>>(bx, stats, TT);
    mma_conv<3><<<dim3(TT/128, HH/64, BB), blk>>>(bx, enc_post_w, enc_post_b, by,
        nullptr, in_mask, stats, enc_last_g, enc_last_b, in_mask, HH, HH, TT, 1.f, 0);

    // ---- group by segments -> [B,H,L] into bx ----
    seg_zero<<<((int)SZ_SEG + 255)/256, 256>>>(seg, cnt);
    seg_scatter<<<dim3(TT, BB), HH>>>(by, mel2ph, seg, cnt);
    seg_div<<<(BB*HH*LL + 255)/256, 256>>>(seg, cnt, bx);

    // ---- postnet (T = LL) ----
    for (int i = 0; i < NLB; i++) {
        ln_stats<<<(BB*LL + 255)/256, 256>>>(bx, stats, LL);
        mma_conv<3><<<dim3(LL/128, HH2/64, BB), blk>>>(bx, pn_w1 + (size_t)i*HH2*HH*3,
            pn_b1 + i*HH2, bm, nullptr, nullptr,
            stats, pn_ln_g + i*HH, pn_ln_b + i*HH, nullptr, HH, HH2, LL, scale, 1);
        mma_conv<1><<<dim3(LL/128, HH/64, BB), blk>>>(bm, pn_w2 + (size_t)i*HH*HH2,
            pn_b2 + i*HH, bx, bx, ph_mask,
            nullptr, nullptr, nullptr, nullptr, HH2, HH, LL, 1.f, 0);
    }
    ln_stats<<<(BB*LL + 255)/256, 256>>>(bx, stats, LL);
    mma_conv<3><<<dim3(LL/128, HH/64, BB), blk>>>(bx, pn_post_w, pn_post_b, by,
        nullptr, ph_mask, stats, pn_last_g, pn_last_b, ph_mask, HH, HH, LL, 1.f, 0);

    // ---- proj_in -> VQ -> proj_out ----
    mma_conv<1><<<dim3(LL/128, CVQd/64, BB), blk>>>(by, proj_in_w, proj_in_b, bz,
        nullptr, nullptr, nullptr, nullptr, nullptr, nullptr, HH, CVQd, LL, 1.f, 0);
    loss_init<<<1, 32>>>(loss);
    vq_kernel<<<dim3(LL, BB), 128>>>(bz, codebook, bq, out + (size_t)BB*HH*LL + 1, loss);
    mma_conv<1><<<dim3(LL/128, HH/64, BB), blk>>>(bq, proj_out_w, proj_out_b, out,
        nullptr, nullptr, nullptr, nullptr, nullptr, nullptr, CVQd, HH, LL, 1.f, 0);
    loss_fin<<<1, 1>>>(loss, out + (size_t)BB*HH*LL);
}

// round 5
// speedup vs baseline: 1.9082x; 1.9082x over previous
#include <cuda_runtime.h>
#include <math.h>
#include <stdint.h>

// ---------------- problem constants ----------------
#define BB   16
#define TT   2048
#define LL   512
#define HH   256
#define HH2  512
#define CVQd 64
#define NLB  10   // NL * NB

// ---------------- sizes ----------------
#define SZ_BHT  ((size_t)BB*HH*TT)         // 8,388,608
#define SZ_BMT  ((size_t)BB*HH2*TT)        // 16,777,216
#define SZ_X    ((size_t)BB*80*TT)         // 2,621,440
#define SZ_BHL  ((size_t)BB*HH*LL)         // 2,097,152
#define SZ_SEG  ((size_t)BB*HH*(LL+1))
#define SZ_CNT  ((size_t)BB*(LL+1))
#define SZ_BZL  ((size_t)BB*CVQd*LL)

// weight plane sizes (floats)
#define WSZ_CIN ((size_t)HH*80)
#define WSZ_E1  ((size_t)NLB*HH2*HH*3)
#define WSZ_E2  ((size_t)NLB*HH*HH2)
#define WSZ_EP  ((size_t)HH*HH*3)
#define WSZ_PI  ((size_t)CVQd*HH)
#define WSZ_PO  ((size_t)HH*CVQd)
#define WTOT    (WSZ_CIN + 2*(WSZ_E1 + WSZ_E2 + WSZ_EP) + WSZ_PI + WSZ_PO)

// scratch offsets (floats)
#define O_BX   ((size_t)0)
#define O_BY   (O_BX  + SZ_BHT)
#define O_BNH  (O_BY  + SZ_BHT)
#define O_BNL  (O_BNH + SZ_BHT)
#define O_BMH  (O_BNL + SZ_BHT)
#define O_BML  (O_BMH + SZ_BMT)
#define O_XH   (O_BML + SZ_BMT)
#define O_XL   (O_XH  + SZ_X)
#define O_BYH  (O_XL  + SZ_X)
#define O_BYL  (O_BYH + SZ_BHL)
#define O_SEG  (O_BYL + SZ_BHL)
#define O_CNT  (O_SEG + SZ_SEG)
#define O_BZ   (O_CNT + SZ_CNT)
#define O_QH   (O_BZ  + SZ_BZL)
#define O_QL   (O_QH  + SZ_BZL)
#define O_LOSS (O_QL  + SZ_BZL)
#define O_WH   (O_LOSS + 16)
#define O_WL   (O_WH  + WTOT)
#define SCRATCH_TOT (O_WL + WTOT)

__device__ __align__(16) float g_scratch[SCRATCH_TOT];

// weight offsets inside wh/wl planes
#define OW_CIN ((size_t)0)
#define OW_E1  (OW_CIN + WSZ_CIN)
#define OW_E2  (OW_E1 + WSZ_E1)
#define OW_EP  (OW_E2 + WSZ_E2)
#define OW_P1  (OW_EP + WSZ_EP)
#define OW_P2  (OW_P1 + WSZ_E1)
#define OW_PP  (OW_P2 + WSZ_E2)
#define OW_PI  (OW_PP + WSZ_EP)
#define OW_PO  (OW_PI + WSZ_PI)

// ---------------- helpers ----------------
__device__ __forceinline__ float tf32_rna(float x) {
    uint32_t u;
    asm("cvt.rna.tf32.f32 %0, %1;" : "=r"(u) : "f"(x));
    return __uint_as_float(u);
}

#define MMA_TF32(C, A, B)                                                        \
    asm volatile("mma.sync.aligned.m16n8k8.row.col.f32.tf32.tf32.f32 "           \
        "{%0,%1,%2,%3}, {%4,%5,%6,%7}, {%8,%9}, {%0,%1,%2,%3};"                  \
        : "+f"((C)[0]), "+f"((C)[1]), "+f"((C)[2]), "+f"((C)[3])                  \
        : "r"((A)[0]), "r"((A)[1]), "r"((A)[2]), "r"((A)[3]),                     \
          "r"((B)[0]), "r"((B)[1]))

// ---------------- prepass: split fp32 -> tf32 hi/lo ----------------
__global__ void split_hilo(const float* __restrict__ s, float* __restrict__ dh,
                           float* __restrict__ dl, int n)
{
    int i = blockIdx.x * blockDim.x + threadIdx.x;
    if (i >= n) return;
    float v = s[i];
    float h = tf32_rna(v);
    dh[i] = h;
    dl[i] = tf32_rna(v - h);
}

// ---------------- prepass: weights -> pre-tiled hi/lo ----------------
// src order: [layer][co][ci][tap]; dst: [layer][co][cib*16*KS + tap*16 + ci%16]
__global__ void prep_w(const float* __restrict__ w, float* __restrict__ oh,
                       float* __restrict__ ol, int total, int Cout, int Cin, int KS)
{
    int idx = blockIdx.x * blockDim.x + threadIdx.x;
    if (idx >= total) return;
    int per_layer = Cout * Cin * KS;
    int layer = idx / per_layer;
    int r = idx - layer * per_layer;
    int co = r / (Cin * KS);
    int r2 = r - co * (Cin * KS);
    int ci = r2 / KS;
    int tap = r2 - ci * KS;
    float v = w[idx];
    int kidx = (ci >> 4) * (16 * KS) + tap * 16 + (ci & 15);
    size_t o = ((size_t)layer * Cout + co) * (size_t)(Cin * KS) + kidx;
    float h = tf32_rna(v);
    oh[o] = h;
    ol[o] = tf32_rna(v - h);
}

// ---------------- LayerNorm over channel dim -> hi/lo outputs ----------------
__global__ void ln_kernel(const float* __restrict__ in, float* __restrict__ outh,
                          float* __restrict__ outl,
                          const float* __restrict__ gma, const float* __restrict__ bta,
                          const float* __restrict__ mask, int Tdim)
{
    int idx = blockIdx.x * blockDim.x + threadIdx.x;
    if (idx >= BB * Tdim) return;
    int b = idx / Tdim, t = idx - b * Tdim;
    const float* p = in + (size_t)b * HH * Tdim + t;
    float s = 0.f, s2 = 0.f;
    #pragma unroll 8
    for (int c = 0; c < HH; c++) { float v = p[(size_t)c * Tdim]; s += v; s2 += v * v; }
    float mean = s * (1.f / HH);
    float var  = s2 * (1.f / HH) - mean * mean;
    float r = rsqrtf(var + 1e-5f);
    float mk = mask ? mask[b * Tdim + t] : 1.f;
    size_t base = (size_t)b * HH * Tdim + t;
    #pragma unroll 8
    for (int c = 0; c < HH; c++) {
        float v = p[(size_t)c * Tdim];
        float val = ((v - mean) * r * gma[c] + bta[c]) * mk;
        float h = tf32_rna(val);
        outh[base + (size_t)c * Tdim] = h;
        outl[base + (size_t)c * Tdim] = tf32_rna(val - h);
    }
}

// ---------------- 3xTF32 tensor-core conv GEMM, cp.async double-buffered ----------------
// BM=64 (Cout) x BN=128 (T), ci-block outer (16 ci), KS taps inner.
// 256 threads = 8 warps (2M x 4N). Inputs pre-split hi/lo. Weights pre-tiled.
template<int KS>
__global__ void __launch_bounds__(256, 2)
mma_conv(const float* __restrict__ inh, const float* __restrict__ inl,
         const float* __restrict__ wh, const float* __restrict__ wl,
         const float* __restrict__ bias,
         float* outF, float* outH, float* outL,
         const float* residual, const float* __restrict__ mask,
         int Cin, int Cout, int Tdim, float scale, int dogelu)
{
    extern __shared__ float sm[];
    constexpr int ASZ = KS * 1280;      // per plane per buf: KS taps x [64][20]
    constexpr int AOFF_TOT = 4 * ASZ;   // 2 buf x 2 plane
    // B: per plane per buf 16*168 = 2688 floats; data cols [0,144) = t in [tg-16, tg+128)

    const int b   = blockIdx.z;
    const int cog = blockIdx.y * 64;
    const int tg  = blockIdx.x * 128;
    const int tid = threadIdx.x;
    const int lane = tid & 31, wid = tid >> 5;
    const int wm = wid >> 2, wn = wid & 3;
    const int g = lane >> 2, th = lane & 3;

    const int Ktot = Cin * KS;
    const int ncib = Cin >> 4;
    const size_t inOffB = (size_t)b * Cin * Tdim;

    unsigned smb;
    {
        void* p = sm;
        smb = (unsigned)__cvta_generic_to_shared(p);
    }

    float c[2][4][4];
    #pragma unroll
    for (int i = 0; i < 2; i++)
        #pragma unroll
        for (int j = 0; j < 4; j++)
            #pragma unroll
            for (int k = 0; k < 4; k++) c[i][j][k] = 0.f;

    // ---------- stage loader (cp.async) ----------
    auto load_stage = [&](int cib, int buf) {
        // A: 2 planes x 64 m x (4*KS) 16B-chunks
        const int ATOT = 512 * KS;
        for (int ic = tid; ic < ATOT; ic += 256) {
            int plane = ic / (256 * KS);
            int r = ic - plane * (256 * KS);
            int m = r / (4 * KS);
            int q = r - m * (4 * KS);
            int tap = q >> 2, j = q & 3;
            const float* src = (plane ? wl : wh)
                + (size_t)(cog + m) * Ktot + cib * (16 * KS) + tap * 16 + j * 4;
            unsigned dst = smb + 4u * (unsigned)((buf * 2 + plane) * ASZ + tap * 1280 + m * 20 + j * 4);
            asm volatile("cp.async.ca.shared.global [%0], [%1], 16;" :: "r"(dst), "l"(src));
        }
        // B: 2 planes x 16 rows x 36 chunks (144 floats = [tg-16, tg+128))
        for (int ic = tid; ic < 1152; ic += 256) {
            int plane = ic / 576;
            int r = ic - plane * 576;
            int row = r / 36, cch = r - row * 36;
            int t0 = tg - 16 + cch * 4;
            const float* src = (plane ? inl : inh) + inOffB + (size_t)(cib * 16 + row) * Tdim + t0;
            unsigned dst = smb + 4u * (unsigned)(AOFF_TOT + (buf * 2 + plane) * 2688 + row * 168 + cch * 4);
            int ssz = (t0 >= 0) ? 16 : 0;
            asm volatile("cp.async.ca.shared.global [%0], [%1], 16, %2;" :: "r"(dst), "l"(src), "r"(ssz));
        }
    };

    // ---------- compute one staged ci-block ----------
    auto compute = [&](int buf) {
        const float* Bh = sm + AOFF_TOT + (buf * 2 + 0) * 2688;
        const float* Bl = sm + AOFF_TOT + (buf * 2 + 1) * 2688;
        #pragma unroll
        for (int tap = 0; tap < KS; tap++) {
            const float* Ah = sm + (buf * 2 + 0) * ASZ + tap * 1280;
            const float* Al = sm + (buf * 2 + 1) * ASZ + tap * 1280;
            const int tl0 = tap - (KS - 1) + 16;
            #pragma unroll
            for (int k8 = 0; k8 < 2; k8++) {
                const int k0 = k8 * 8;
                uint32_t ah[2][4], al[2][4];
                #pragma unroll
                for (int mf = 0; mf < 2; mf++) {
                    int m = wm * 32 + mf * 16 + g;
                    ah[mf][0] = __float_as_uint(Ah[m * 20 + k0 + th]);
                    ah[mf][1] = __float_as_uint(Ah[(m + 8) * 20 + k0 + th]);
                    ah[mf][2] = __float_as_uint(Ah[m * 20 + k0 + th + 4]);
                    ah[mf][3] = __float_as_uint(Ah[(m + 8) * 20 + k0 + th + 4]);
                    al[mf][0] = __float_as_uint(Al[m * 20 + k0 + th]);
                    al[mf][1] = __float_as_uint(Al[(m + 8) * 20 + k0 + th]);
                    al[mf][2] = __float_as_uint(Al[m * 20 + k0 + th + 4]);
                    al[mf][3] = __float_as_uint(Al[(m + 8) * 20 + k0 + th + 4]);
                }
                #pragma unroll
                for (int nf = 0; nf < 4; nf++) {
                    int n = wn * 32 + nf * 8 + g;
                    uint32_t bh[2], bl[2];
                    bh[0] = __float_as_uint(Bh[(k0 + th) * 168 + n + tl0]);
                    bh[1] = __float_as_uint(Bh[(k0 + th + 4) * 168 + n + tl0]);
                    bl[0] = __float_as_uint(Bl[(k0 + th) * 168 + n + tl0]);
                    bl[1] = __float_as_uint(Bl[(k0 + th + 4) * 168 + n + tl0]);
                    #pragma unroll
                    for (int mf = 0; mf < 2; mf++) {
                        MMA_TF32(c[mf][nf], ah[mf], bh);
                        MMA_TF32(c[mf][nf], ah[mf], bl);
                        MMA_TF32(c[mf][nf], al[mf], bh);
                    }
                }
            }
        }
    };

    // ---------- pipelined mainloop ----------
    load_stage(0, 0);
    asm volatile("cp.async.commit_group;");
    for (int cib = 0; cib < ncib; cib++) {
        int buf = cib & 1;
        bool more = (cib + 1 < ncib);
        if (more) {
            load_stage(cib + 1, buf ^ 1);
            asm volatile("cp.async.commit_group;");
            asm volatile("cp.async.wait_group 1;");
        } else {
            asm volatile("cp.async.wait_group 0;");
        }
        __syncthreads();
        compute(buf);
        __syncthreads();
    }

    // ---------- epilogue ----------
    #pragma unroll
    for (int mf = 0; mf < 2; mf++) {
        int m0 = cog + wm * 32 + mf * 16 + g;
        float bi0 = bias[m0], bi1 = bias[m0 + 8];
        #pragma unroll
        for (int nf = 0; nf < 4; nf++) {
            int t0 = tg + wn * 32 + nf * 8 + 2 * th;
            #pragma unroll
            for (int half = 0; half < 2; half++) {
                int m = half ? m0 + 8 : m0;
                float bi = half ? bi1 : bi0;
                float v0 = (c[mf][nf][half * 2 + 0] + bi) * scale;
                float v1 = (c[mf][nf][half * 2 + 1] + bi) * scale;
                if (dogelu) {
                    v0 = 0.5f * v0 * (1.f + erff(v0 * 0.70710678118654752f));
                    v1 = 0.5f * v1 * (1.f + erff(v1 * 0.70710678118654752f));
                }
                size_t oi = ((size_t)b * Cout + m) * Tdim + t0;
                if (residual) { v0 += residual[oi]; v1 += residual[oi + 1]; }
                if (mask) {
                    v0 *= mask[b * Tdim + t0];
                    v1 *= mask[b * Tdim + t0 + 1];
                }
                if (outF) { outF[oi] = v0; outF[oi + 1] = v1; }
                if (outH) {
                    float h0 = tf32_rna(v0), h1 = tf32_rna(v1);
                    outH[oi] = h0;     outH[oi + 1] = h1;
                    outL[oi] = tf32_rna(v0 - h0);
                    outL[oi + 1] = tf32_rna(v1 - h1);
                }
            }
        }
    }
}

// ---------------- group_by_segs ----------------
__global__ void seg_zero(float* seg, float* cnt)
{
    int i = blockIdx.x * blockDim.x + threadIdx.x;
    if (i < (int)SZ_SEG) seg[i] = 0.f;
    if (i < (int)SZ_CNT) cnt[i] = 0.f;
}
__global__ void seg_scatter(const float* __restrict__ in, const int* __restrict__ mel2ph,
                            float* seg, float* cnt)
{
    int t = blockIdx.x, b = blockIdx.y, c = threadIdx.x;
    int ph = mel2ph[b * TT + t];
    if (ph < 1 || ph > LL) return;
    float v = in[((size_t)b * HH + c) * TT + t];
    atomicAdd(&seg[((size_t)b * HH + c) * (LL + 1) + ph], v);
    if (c == 0) atomicAdd(&cnt[b * (LL + 1) + ph], 1.f);
}
__global__ void seg_div(const float* __restrict__ seg, const float* __restrict__ cnt,
                        float* __restrict__ outg)
{
    int i = blockIdx.x * blockDim.x + threadIdx.x;
    if (i >= BB * HH * LL) return;
    int l = i % LL; int bc = i / LL; int c = bc % HH; int b = bc / HH;
    float s = seg[((size_t)b * HH + c) * (LL + 1) + l + 1];
    float n = fmaxf(cnt[b * (LL + 1) + l + 1], 1.f);
    outg[i] = s / n;
}

// ---------------- VQ ----------------
__global__ void loss_init(float* loss) { if (threadIdx.x == 0) *loss = 0.f; }

__global__ void vq_kernel(const float* __restrict__ z, const float* __restrict__ cb,
                          float* __restrict__ qh, float* __restrict__ ql,
                          float* __restrict__ outIdx, float* loss)
{
    __shared__ float zsh[64];
    __shared__ float dsh[128];
    __shared__ int   ish[128];
    int l = blockIdx.x, b = blockIdx.y, tid = threadIdx.x;
    if (tid < 64) zsh[tid] = z[((size_t)b * CVQd + tid) * LL + l];
    __syncthreads();
    float x2 = 0.f, dot = 0.f, c2 = 0.f;
    #pragma unroll 8
    for (int c = 0; c < 64; c++) {
        float zv = zsh[c]; float cv = cb[tid * 64 + c];
        x2 += zv * zv; dot += zv * cv; c2 += cv * cv;
    }
    dsh[tid] = x2 - 2.f * dot + c2;
    ish[tid] = tid;
    __syncthreads();
    for (int s = 64; s > 0; s >>= 1) {
        if (tid < s) {
            float d2 = dsh[tid + s]; int i2 = ish[tid + s];
            if (d2 < dsh[tid] || (d2 == dsh[tid] && i2 < ish[tid])) { dsh[tid] = d2; ish[tid] = i2; }
        }
        __syncthreads();
    }
    int best = ish[0];
    __syncthreads();
    float part = 0.f;
    if (tid < 64) {
        float qv = cb[best * 64 + tid];
        size_t oi = ((size_t)b * CVQd + tid) * LL + l;
        float h = tf32_rna(qv);
        qh[oi] = h;
        ql[oi] = tf32_rna(qv - h);
        float dd = zsh[tid] - qv;
        part = dd * dd;
    }
    dsh[tid] = part;
    __syncthreads();
    for (int s = 64; s > 0; s >>= 1) { if (tid < s) dsh[tid] += dsh[tid + s]; __syncthreads(); }
    if (tid == 0) {
        atomicAdd(loss, dsh[0]);
        outIdx[b * LL + l] = (float)best;
    }
}

__global__ void loss_fin(const float* loss, float* out)
{
    out[0] = loss[0] * 0.25f / (float)(BB * LL * CVQd);
}

// ---------------- launch ----------------
extern "C" void kernel_launch(void* const* d_in, const int* in_sizes, int n_in,
                              void* d_out, int out_size)
{
    float* scratch = nullptr;
    cudaGetSymbolAddress((void**)&scratch, g_scratch);
    float* bx  = scratch + O_BX;
    float* by  = scratch + O_BY;
    float* bnh = scratch + O_BNH;
    float* bnl = scratch + O_BNL;
    float* bmh = scratch + O_BMH;
    float* bml = scratch + O_BML;
    float* xh  = scratch + O_XH;
    float* xl  = scratch + O_XL;
    float* byh = scratch + O_BYH;
    float* byl = scratch + O_BYL;
    float* seg = scratch + O_SEG;
    float* cnt = scratch + O_CNT;
    float* bz  = scratch + O_BZ;
    float* qh  = scratch + O_QH;
    float* ql  = scratch + O_QL;
    float* loss = scratch + O_LOSS;
    float* wh  = scratch + O_WH;
    float* wl  = scratch + O_WL;

    const float* x        = (const float*)d_in[0];
    const float* in_mask  = (const float*)d_in[1];
    const int*   mel2ph   = (const int*)  d_in[2];
    const float* ph_mask  = (const float*)d_in[3];
    const float* conv_in_w = (const float*)d_in[4];
    const float* conv_in_b = (const float*)d_in[5];
    const float* enc_ln_g = (const float*)d_in[6];
    const float* enc_ln_b = (const float*)d_in[7];
    const float* enc_w1   = (const float*)d_in[8];
    const float* enc_b1   = (const float*)d_in[9];
    const float* enc_w2   = (const float*)d_in[10];
    const float* enc_b2   = (const float*)d_in[11];
    const float* enc_last_g = (const float*)d_in[12];
    const float* enc_last_b = (const float*)d_in[13];
    const float* enc_post_w = (const float*)d_in[14];
    const float* enc_post_b = (const float*)d_in[15];
    const float* pn_ln_g = (const float*)d_in[16];
    const float* pn_ln_b = (const float*)d_in[17];
    const float* pn_w1   = (const float*)d_in[18];
    const float* pn_b1   = (const float*)d_in[19];
    const float* pn_w2   = (const float*)d_in[20];
    const float* pn_b2   = (const float*)d_in[21];
    const float* pn_last_g = (const float*)d_in[22];
    const float* pn_last_b = (const float*)d_in[23];
    const float* pn_post_w = (const float*)d_in[24];
    const float* pn_post_b = (const float*)d_in[25];
    const float* proj_in_w  = (const float*)d_in[26];
    const float* proj_in_b  = (const float*)d_in[27];
    const float* proj_out_w = (const float*)d_in[28];
    const float* proj_out_b = (const float*)d_in[29];
    const float* codebook   = (const float*)d_in[30];

    float* out = (float*)d_out;
    const float scale = 0.57735026918962576f;   // 3^-0.5

    // dynamic smem sizes
    const int SM3 = (4 * 3 * 1280 + 4 * 2688) * 4;   // 104448 B
    const int SM1 = (4 * 1 * 1280 + 4 * 2688) * 4;   //  63488 B
    cudaFuncSetAttribute(mma_conv<3>, cudaFuncAttributeMaxDynamicSharedMemorySize, SM3);
    cudaFuncSetAttribute(mma_conv<1>, cudaFuncAttributeMaxDynamicSharedMemorySize, SM1);

    dim3 blk(256);

    // ---- prepass: split inputs / pre-tile weights ----
    split_hilo<<<((int)SZ_X + 255) / 256, 256>>>(x, xh, xl, (int)SZ_X);
    prep_w<<<((int)WSZ_CIN + 255) / 256, 256>>>(conv_in_w, wh + OW_CIN, wl + OW_CIN,
                                                (int)WSZ_CIN, HH, 80, 1);
    prep_w<<<((int)WSZ_E1 + 255) / 256, 256>>>(enc_w1, wh + OW_E1, wl + OW_E1,
                                               (int)WSZ_E1, HH2, HH, 3);
    prep_w<<<((int)WSZ_E2 + 255) / 256, 256>>>(enc_w2, wh + OW_E2, wl + OW_E2,
                                               (int)WSZ_E2, HH, HH2, 1);
    prep_w<<<((int)WSZ_EP + 255) / 256, 256>>>(enc_post_w, wh + OW_EP, wl + OW_EP,
                                               (int)WSZ_EP, HH, HH, 3);
    prep_w<<<((int)WSZ_E1 + 255) / 256, 256>>>(pn_w1, wh + OW_P1, wl + OW_P1,
                                               (int)WSZ_E1, HH2, HH, 3);
    prep_w<<<((int)WSZ_E2 + 255) / 256, 256>>>(pn_w2, wh + OW_P2, wl + OW_P2,
                                               (int)WSZ_E2, HH, HH2, 1);
    prep_w<<<((int)WSZ_EP + 255) / 256, 256>>>(pn_post_w, wh + OW_PP, wl + OW_PP,
                                               (int)WSZ_EP, HH, HH, 3);
    prep_w<<<((int)WSZ_PI + 255) / 256, 256>>>(proj_in_w, wh + OW_PI, wl + OW_PI,
                                               (int)WSZ_PI, CVQd, HH, 1);
    prep_w<<<((int)WSZ_PO + 255) / 256, 256>>>(proj_out_w, wh + OW_PO, wl + OW_PO,
                                               (int)WSZ_PO, HH, CVQd, 1);

    // ---- encoder (T = TT) ----
    mma_conv<1><<<dim3(TT/128, HH/64, BB), blk, SM1>>>(xh, xl, wh + OW_CIN, wl + OW_CIN,
        conv_in_b, bx, nullptr, nullptr, nullptr, in_mask, 80, HH, TT, 1.f, 0);
    for (int i = 0; i < NLB; i++) {
        ln_kernel<<<(BB*TT + 255)/256, 256>>>(bx, bnh, bnl,
            enc_ln_g + i*HH, enc_ln_b + i*HH, nullptr, TT);
        mma_conv<3><<<dim3(TT/128, HH2/64, BB), blk, SM3>>>(bnh, bnl,
            wh + OW_E1 + (size_t)i*HH2*HH*3, wl + OW_E1 + (size_t)i*HH2*HH*3,
            enc_b1 + i*HH2, nullptr, bmh, bml, nullptr, nullptr, HH, HH2, TT, scale, 1);
        mma_conv<1><<<dim3(TT/128, HH/64, BB), blk, SM1>>>(bmh, bml,
            wh + OW_E2 + (size_t)i*HH*HH2, wl + OW_E2 + (size_t)i*HH*HH2,
            enc_b2 + i*HH, bx, nullptr, nullptr, bx, in_mask, HH2, HH, TT, 1.f, 0);
    }
    ln_kernel<<<(BB*TT + 255)/256, 256>>>(bx, bnh, bnl, enc_last_g, enc_last_b, in_mask, TT);
    mma_conv<3><<<dim3(TT/128, HH/64, BB), blk, SM3>>>(bnh, bnl, wh + OW_EP, wl + OW_EP,
        enc_post_b, by, nullptr, nullptr, nullptr, in_mask, HH, HH, TT, 1.f, 0);

    // ---- group by segments -> [B,H,L] into bx ----
    seg_zero<<<((int)SZ_SEG + 255)/256, 256>>>(seg, cnt);
    seg_scatter<<<dim3(TT, BB), HH>>>(by, mel2ph, seg, cnt);
    seg_div<<<(BB*HH*LL + 255)/256, 256>>>(seg, cnt, bx);

    // ---- postnet (T = LL) ----
    for (int i = 0; i < NLB; i++) {
        ln_kernel<<<(BB*LL + 255)/256, 256>>>(bx, bnh, bnl,
            pn_ln_g + i*HH, pn_ln_b + i*HH, nullptr, LL);
        mma_conv<3><<<dim3(LL/128, HH2/64, BB), blk, SM3>>>(bnh, bnl,
            wh + OW_P1 + (size_t)i*HH2*HH*3, wl + OW_P1 + (size_t)i*HH2*HH*3,
            pn_b1 + i*HH2, nullptr, bmh, bml, nullptr, nullptr, HH, HH2, LL, scale, 1);
        mma_conv<1><<<dim3(LL/128, HH/64, BB), blk, SM1>>>(bmh, bml,
            wh + OW_P2 + (size_t)i*HH*HH2, wl + OW_P2 + (size_t)i*HH*HH2,
            pn_b2 + i*HH, bx, nullptr, nullptr, bx, ph_mask, HH2, HH, LL, 1.f, 0);
    }
    ln_kernel<<<(BB*LL + 255)/256, 256>>>(bx, bnh, bnl, pn_last_g, pn_last_b, ph_mask, LL);
    mma_conv<3><<<dim3(LL/128, HH/64, BB), blk, SM3>>>(bnh, bnl, wh + OW_PP, wl + OW_PP,
        pn_post_b, nullptr, byh, byl, nullptr, ph_mask, HH, HH, LL, 1.f, 0);

    // ---- proj_in -> VQ -> proj_out ----
    mma_conv<1><<<dim3(LL/128, CVQd/64, BB), blk, SM1>>>(byh, byl, wh + OW_PI, wl + OW_PI,
        proj_in_b, bz, nullptr, nullptr, nullptr, nullptr, HH, CVQd, LL, 1.f, 0);
    loss_init<<<1, 32>>>(loss);
    vq_kernel<<<dim3(LL, BB), 128>>>(bz, codebook, qh, ql, out + (size_t)BB*HH*LL + 1, loss);
    mma_conv<1><<<dim3(LL/128, HH/64, BB), blk, SM1>>>(qh, ql, wh + OW_PO, wl + OW_PO,
        proj_out_b, out, nullptr, nullptr, nullptr, nullptr, CVQd, HH, LL, 1.f, 0);
    loss_fin<<<1, 1>>>(loss, out + (size_t)BB*HH*LL);
}

// round 6
// speedup vs baseline: 3.0548x; 1.6009x over previous
#include <cuda_runtime.h>
#include <cuda_fp16.h>
#include <math.h>
#include <stdint.h>

// ---------------- problem constants ----------------
#define BB   16
#define TT   2048
#define LL   512
#define HH   256
#define HH2  512
#define CVQd 64
#define NLB  10   // NL * NB

// ---------------- sizes (floats) ----------------
#define SZ_BHT  ((size_t)BB*HH*TT)
#define SZ_BMT  ((size_t)BB*HH2*TT)
#define SZ_X    ((size_t)BB*80*TT)
#define SZ_BHL  ((size_t)BB*HH*LL)
#define SZ_SEG  ((size_t)BB*HH*(LL+1))
#define SZ_CNT  ((size_t)BB*(LL+1))
#define SZ_BZL  ((size_t)BB*CVQd*LL)

// weight plane sizes (elements)
#define WSZ_CIN ((size_t)HH*80)
#define WSZ_E1  ((size_t)NLB*HH2*HH*3)
#define WSZ_E2  ((size_t)NLB*HH*HH2)
#define WSZ_EP  ((size_t)HH*HH*3)
#define WSZ_PI  ((size_t)CVQd*HH)
#define WSZ_PO  ((size_t)HH*CVQd)
#define WTOT    (WSZ_CIN + 2*(WSZ_E1 + WSZ_E2 + WSZ_EP) + WSZ_PI + WSZ_PO)

// scratch offsets (float units). half planes take size/2 floats.
#define O_BX   ((size_t)0)
#define O_BY   (O_BX  + SZ_BHT)
#define O_BNH  (O_BY  + SZ_BHT)
#define O_BNL  (O_BNH + SZ_BHT/2)
#define O_BMH  (O_BNL + SZ_BHT/2)
#define O_BML  (O_BMH + SZ_BMT/2)
#define O_XH   (O_BML + SZ_BMT/2)
#define O_XL   (O_XH  + SZ_X/2)
#define O_BYH  (O_XL  + SZ_X/2)
#define O_BYL  (O_BYH + SZ_BHL/2)
#define O_SEG  (O_BYL + SZ_BHL/2)
#define O_CNT  (O_SEG + SZ_SEG)
#define O_BZ   (O_CNT + SZ_CNT)
#define O_QH   (O_BZ  + SZ_BZL)
#define O_QL   (O_QH  + SZ_BZL/2)
#define O_LOSS (O_QL  + SZ_BZL/2)
#define O_WH   (O_LOSS + 16)
#define O_WL   (O_WH  + WTOT/2)
#define SCRATCH_TOT (O_WL + WTOT/2)

__device__ __align__(16) float g_scratch[SCRATCH_TOT];

// weight offsets inside wh/wl planes (element units)
#define OW_CIN ((size_t)0)
#define OW_E1  (OW_CIN + WSZ_CIN)
#define OW_E2  (OW_E1 + WSZ_E1)
#define OW_EP  (OW_E2 + WSZ_E2)
#define OW_P1  (OW_EP + WSZ_EP)
#define OW_P2  (OW_P1 + WSZ_E1)
#define OW_PP  (OW_P2 + WSZ_E2)
#define OW_PI  (OW_PP + WSZ_EP)
#define OW_PO  (OW_PI + WSZ_PI)

// ---------------- helpers ----------------
__device__ __forceinline__ void split_f16(float v, __half& h, __half& l)
{
    h = __float2half_rn(v);
    l = __float2half_rn(v - __half2float(h));
}

#define MMA_F16(C, A, B)                                                         \
    asm volatile("mma.sync.aligned.m16n8k16.row.col.f32.f16.f16.f32 "            \
        "{%0,%1,%2,%3}, {%4,%5,%6,%7}, {%8,%9}, {%0,%1,%2,%3};"                  \
        : "+f"((C)[0]), "+f"((C)[1]), "+f"((C)[2]), "+f"((C)[3])                  \
        : "r"((A)[0]), "r"((A)[1]), "r"((A)[2]), "r"((A)[3]),                     \
          "r"((B)[0]), "r"((B)[1]))

// pair-interleaved activation plane: half idx = b*C*T + (c>>1)*2T + 2t + (c&1)

// ---------------- prepass: x -> pair-interleaved fp16 hi/lo ----------------
__global__ void split_x(const float* __restrict__ s, __half* __restrict__ dh,
                        __half* __restrict__ dl, int C, int Tdim, int n)
{
    int i = blockIdx.x * blockDim.x + threadIdx.x;
    if (i >= n) return;
    int b = i / (C * Tdim);
    int r = i - b * C * Tdim;
    int c = r / Tdim, t = r - c * Tdim;
    __half h, l;
    split_f16(s[i], h, l);
    size_t o = (size_t)b * C * Tdim + (size_t)(c >> 1) * 2 * Tdim + 2 * t + (c & 1);
    dh[o] = h; dl[o] = l;
}

// ---------------- prepass: weights -> pre-tiled fp16 hi/lo ----------------
// src [layer][co][ci][tap] -> dst [layer][co][(ci>>4)*16KS + tap*16 + (ci&15)]
__global__ void prep_w(const float* __restrict__ w, __half* __restrict__ oh,
                       __half* __restrict__ ol, int total, int Cout, int Cin, int KS)
{
    int idx = blockIdx.x * blockDim.x + threadIdx.x;
    if (idx >= total) return;
    int per_layer = Cout * Cin * KS;
    int layer = idx / per_layer;
    int r = idx - layer * per_layer;
    int co = r / (Cin * KS);
    int r2 = r - co * (Cin * KS);
    int ci = r2 / KS;
    int tap = r2 - ci * KS;
    __half h, l;
    split_f16(w[idx], h, l);
    int kidx = (ci >> 4) * (16 * KS) + tap * 16 + (ci & 15);
    size_t o = ((size_t)layer * Cout + co) * (size_t)(Cin * KS) + kidx;
    oh[o] = h; ol[o] = l;
}

// ---------------- LayerNorm -> pair-interleaved fp16 hi/lo ----------------
__global__ void ln_kernel(const float* __restrict__ in, __half* __restrict__ outh,
                          __half* __restrict__ outl,
                          const float* __restrict__ gma, const float* __restrict__ bta,
                          const float* __restrict__ mask, int Tdim)
{
    int idx = blockIdx.x * blockDim.x + threadIdx.x;
    if (idx >= BB * Tdim) return;
    int b = idx / Tdim, t = idx - b * Tdim;
    const float* p = in + (size_t)b * HH * Tdim + t;
    float s = 0.f, s2 = 0.f;
    #pragma unroll 8
    for (int c = 0; c < HH; c++) { float v = p[(size_t)c * Tdim]; s += v; s2 += v * v; }
    float mean = s * (1.f / HH);
    float var  = s2 * (1.f / HH) - mean * mean;
    float r = rsqrtf(var + 1e-5f);
    float mk = mask ? mask[b * Tdim + t] : 1.f;
    size_t base = (size_t)b * HH * Tdim + 2 * t;
    #pragma unroll 4
    for (int c = 0; c < HH; c += 2) {
        float v0 = p[(size_t)c * Tdim];
        float v1 = p[(size_t)(c + 1) * Tdim];
        float a0 = ((v0 - mean) * r * gma[c] + bta[c]) * mk;
        float a1 = ((v1 - mean) * r * gma[c + 1] + bta[c + 1]) * mk;
        __half h0, l0, h1, l1;
        split_f16(a0, h0, l0);
        split_f16(a1, h1, l1);
        size_t o = base + (size_t)(c >> 1) * 2 * Tdim;
        outh[o] = h0; outh[o + 1] = h1;
        outl[o] = l0; outl[o + 1] = l1;
    }
}

// ---------------- fp16-split tensor-core conv GEMM, cp.async double-buffered ----------------
// BM=64 (Cout) x BN=128 (T), ci-block = 16 ci (one k16 step), KS taps inner.
// 256 threads = 8 warps (2M x 4N).
template<int KS>
__global__ void __launch_bounds__(256)
mma_conv(const __half* __restrict__ inh, const __half* __restrict__ inl,
         const __half* __restrict__ wh, const __half* __restrict__ wl,
         const float* __restrict__ bias,
         float* outF, __half* outH, __half* outL,
         const float* residual, const float* __restrict__ mask,
         int Cin, int Cout, int Tdim, float scale, int dogelu)
{
    extern __shared__ uint32_t smu[];
    // A: [buf2][plane2][tapKS][64*12 u32]; B: base + [buf2][plane2][8*152 u32]
    constexpr int A_TAP = 768;             // 64 rows * 12 u32
    constexpr int A_TOT = 4 * KS * A_TAP;  // u32
    constexpr int B_PL  = 1216;            // 8 rows * 152 half2

    const int b   = blockIdx.z;
    const int cog = blockIdx.y * 64;
    const int tg  = blockIdx.x * 128;
    const int tid = threadIdx.x;
    const int lane = tid & 31, wid = tid >> 5;
    const int wm = wid >> 2, wn = wid & 3;
    const int g = lane >> 2, th = lane & 3;

    const int Ktot = Cin * KS;
    const int ncib = Cin >> 4;
    const size_t inOffB = (size_t)b * Cin * Tdim;   // half units

    unsigned smb = (unsigned)__cvta_generic_to_shared(smu);

    float c[2][4][4];
    #pragma unroll
    for (int i = 0; i < 2; i++)
        #pragma unroll
        for (int j = 0; j < 4; j++)
            #pragma unroll
            for (int k = 0; k < 4; k++) c[i][j][k] = 0.f;

    // ---------- stage loader ----------
    auto load_stage = [&](int cib, int buf) {
        // A: 2 planes x KS taps x 64 rows x 2 chunks(16B = 8 halves)
        const int ATOT = 256 * KS;
        for (int ic = tid; ic < ATOT; ic += 256) {
            int plane = ic / (128 * KS);
            int r = ic - plane * (128 * KS);
            int tap = r >> 7;
            int r2 = r & 127;
            int m = r2 >> 1, j = r2 & 1;
            const __half* src = (plane ? wl : wh)
                + (size_t)(cog + m) * Ktot + cib * (16 * KS) + tap * 16 + j * 8;
            unsigned dst = smb + 4u * (unsigned)(((buf * 2 + plane) * KS + tap) * A_TAP + m * 12 + j * 4);
            asm volatile("cp.async.ca.shared.global [%0], [%1], 16;" :: "r"(dst), "l"(src));
        }
        // B: 2 planes x 8 kp rows x 36 chunks (144 t positions = [tg-16, tg+128))
        for (int ic = tid; ic < 576; ic += 256) {
            int plane = ic / 288;
            int r = ic - plane * 288;
            int kp = r / 36, cch = r - kp * 36;
            int t0 = tg - 16 + cch * 4;
            const __half* src = (plane ? inl : inh) + inOffB
                + (size_t)(cib * 8 + kp) * 2 * Tdim + 2 * t0;
            unsigned dst = smb + 4u * (unsigned)(A_TOT + (buf * 2 + plane) * B_PL + kp * 152 + cch * 4);
            int ssz = (t0 >= 0) ? 16 : 0;
            asm volatile("cp.async.ca.shared.global [%0], [%1], 16, %2;" :: "r"(dst), "l"(src), "r"(ssz));
        }
    };

    // ---------- compute one staged ci-block ----------
    auto compute = [&](int buf) {
        const uint32_t* Bh = smu + A_TOT + (buf * 2 + 0) * B_PL;
        const uint32_t* Bl = smu + A_TOT + (buf * 2 + 1) * B_PL;
        #pragma unroll
        for (int tap = 0; tap < KS; tap++) {
            const uint32_t* Awh = smu + ((buf * 2 + 0) * KS + tap) * A_TAP;
            const uint32_t* Awl = smu + ((buf * 2 + 1) * KS + tap) * A_TAP;
            uint32_t ah[2][4], al[2][4];
            #pragma unroll
            for (int mf = 0; mf < 2; mf++) {
                int m = wm * 32 + mf * 16 + g;
                ah[mf][0] = Awh[m * 12 + th];
                ah[mf][1] = Awh[(m + 8) * 12 + th];
                ah[mf][2] = Awh[m * 12 + th + 4];
                ah[mf][3] = Awh[(m + 8) * 12 + th + 4];
                al[mf][0] = Awl[m * 12 + th];
                al[mf][1] = Awl[(m + 8) * 12 + th];
                al[mf][2] = Awl[m * 12 + th + 4];
                al[mf][3] = Awl[(m + 8) * 12 + th + 4];
            }
            const int tl0 = tap - (KS - 1) + 16;
            #pragma unroll
            for (int nf = 0; nf < 4; nf++) {
                int n = wn * 32 + nf * 8 + g + tl0;
                uint32_t bh[2], bl[2];
                bh[0] = Bh[th * 152 + n];
                bh[1] = Bh[(th + 4) * 152 + n];
                bl[0] = Bl[th * 152 + n];
                bl[1] = Bl[(th + 4) * 152 + n];
                #pragma unroll
                for (int mf = 0; mf < 2; mf++) {
                    MMA_F16(c[mf][nf], ah[mf], bh);   // w_h * x_h
                    MMA_F16(c[mf][nf], ah[mf], bl);   // w_h * x_l
                    MMA_F16(c[mf][nf], al[mf], bh);   // w_l * x_h
                }
            }
        }
    };

    // ---------- pipelined mainloop ----------
    load_stage(0, 0);
    asm volatile("cp.async.commit_group;");
    for (int cib = 0; cib < ncib; cib++) {
        int buf = cib & 1;
        bool more = (cib + 1 < ncib);
        if (more) {
            load_stage(cib + 1, buf ^ 1);
            asm volatile("cp.async.commit_group;");
            asm volatile("cp.async.wait_group 1;");
        } else {
            asm volatile("cp.async.wait_group 0;");
        }
        __syncthreads();
        compute(buf);
        __syncthreads();
    }

    // ---------- epilogue ----------
    #pragma unroll
    for (int mf = 0; mf < 2; mf++) {
        int m0 = cog + wm * 32 + mf * 16 + g;
        float bi0 = bias[m0], bi1 = bias[m0 + 8];
        #pragma unroll
        for (int nf = 0; nf < 4; nf++) {
            int t0 = tg + wn * 32 + nf * 8 + 2 * th;
            #pragma unroll
            for (int half = 0; half < 2; half++) {
                int m = half ? m0 + 8 : m0;
                float bi = half ? bi1 : bi0;
                float v0 = (c[mf][nf][half * 2 + 0] + bi) * scale;
                float v1 = (c[mf][nf][half * 2 + 1] + bi) * scale;
                if (dogelu) {
                    v0 = 0.5f * v0 * (1.f + erff(v0 * 0.70710678118654752f));
                    v1 = 0.5f * v1 * (1.f + erff(v1 * 0.70710678118654752f));
                }
                if (residual) {
                    size_t ri = ((size_t)b * Cout + m) * Tdim + t0;
                    v0 += residual[ri]; v1 += residual[ri + 1];
                }
                if (mask) {
                    v0 *= mask[b * Tdim + t0];
                    v1 *= mask[b * Tdim + t0 + 1];
                }
                if (outF) {
                    size_t oi = ((size_t)b * Cout + m) * Tdim + t0;
                    outF[oi] = v0; outF[oi + 1] = v1;
                }
                if (outH) {
                    size_t oi = (size_t)b * Cout * Tdim + (size_t)(m >> 1) * 2 * Tdim
                              + 2 * t0 + (m & 1);
                    __half h0, l0, h1, l1;
                    split_f16(v0, h0, l0);
                    split_f16(v1, h1, l1);
                    outH[oi] = h0; outH[oi + 2] = h1;
                    outL[oi] = l0; outL[oi + 2] = l1;
                }
            }
        }
    }
}

// ---------------- group_by_segs ----------------
__global__ void seg_zero(float* seg, float* cnt)
{
    int i = blockIdx.x * blockDim.x + threadIdx.x;
    if (i < (int)SZ_SEG) seg[i] = 0.f;
    if (i < (int)SZ_CNT) cnt[i] = 0.f;
}
__global__ void seg_scatter(const float* __restrict__ in, const int* __restrict__ mel2ph,
                            float* seg, float* cnt)
{
    int t = blockIdx.x, b = blockIdx.y, c = threadIdx.x;
    int ph = mel2ph[b * TT + t];
    if (ph < 1 || ph > LL) return;
    float v = in[((size_t)b * HH + c) * TT + t];
    atomicAdd(&seg[((size_t)b * HH + c) * (LL + 1) + ph], v);
    if (c == 0) atomicAdd(&cnt[b * (LL + 1) + ph], 1.f);
}
__global__ void seg_div(const float* __restrict__ seg, const float* __restrict__ cnt,
                        float* __restrict__ outg)
{
    int i = blockIdx.x * blockDim.x + threadIdx.x;
    if (i >= BB * HH * LL) return;
    int l = i % LL; int bc = i / LL; int c = bc % HH; int b = bc / HH;
    float s = seg[((size_t)b * HH + c) * (LL + 1) + l + 1];
    float n = fmaxf(cnt[b * (LL + 1) + l + 1], 1.f);
    outg[i] = s / n;
}

// ---------------- VQ ----------------
__global__ void loss_init(float* loss) { if (threadIdx.x == 0) *loss = 0.f; }

__global__ void vq_kernel(const float* __restrict__ z, const float* __restrict__ cb,
                          __half* __restrict__ qh, __half* __restrict__ ql,
                          float* __restrict__ outIdx, float* loss)
{
    __shared__ float zsh[64];
    __shared__ float dsh[128];
    __shared__ int   ish[128];
    int l = blockIdx.x, b = blockIdx.y, tid = threadIdx.x;
    if (tid < 64) zsh[tid] = z[((size_t)b * CVQd + tid) * LL + l];
    __syncthreads();
    float x2 = 0.f, dot = 0.f, c2 = 0.f;
    #pragma unroll 8
    for (int c = 0; c < 64; c++) {
        float zv = zsh[c]; float cv = cb[tid * 64 + c];
        x2 += zv * zv; dot += zv * cv; c2 += cv * cv;
    }
    dsh[tid] = x2 - 2.f * dot + c2;
    ish[tid] = tid;
    __syncthreads();
    for (int s = 64; s > 0; s >>= 1) {
        if (tid < s) {
            float d2 = dsh[tid + s]; int i2 = ish[tid + s];
            if (d2 < dsh[tid] || (d2 == dsh[tid] && i2 < ish[tid])) { dsh[tid] = d2; ish[tid] = i2; }
        }
        __syncthreads();
    }
    int best = ish[0];
    __syncthreads();
    float part = 0.f;
    if (tid < 64) {
        float qv = cb[best * 64 + tid];
        size_t oi = (size_t)b * CVQd * LL + (size_t)(tid >> 1) * 2 * LL + 2 * l + (tid & 1);
        __half h, lo;
        split_f16(qv, h, lo);
        qh[oi] = h; ql[oi] = lo;
        float dd = zsh[tid] - qv;
        part = dd * dd;
    }
    dsh[tid] = part;
    __syncthreads();
    for (int s = 64; s > 0; s >>= 1) { if (tid < s) dsh[tid] += dsh[tid + s]; __syncthreads(); }
    if (tid == 0) {
        atomicAdd(loss, dsh[0]);
        outIdx[b * LL + l] = (float)best;
    }
}

__global__ void loss_fin(const float* loss, float* out)
{
    out[0] = loss[0] * 0.25f / (float)(BB * LL * CVQd);
}

// ---------------- launch ----------------
extern "C" void kernel_launch(void* const* d_in, const int* in_sizes, int n_in,
                              void* d_out, int out_size)
{
    float* scratch = nullptr;
    cudaGetSymbolAddress((void**)&scratch, g_scratch);
    float*  bx  = scratch + O_BX;
    float*  by  = scratch + O_BY;
    __half* bnh = (__half*)(scratch + O_BNH);
    __half* bnl = (__half*)(scratch + O_BNL);
    __half* bmh = (__half*)(scratch + O_BMH);
    __half* bml = (__half*)(scratch + O_BML);
    __half* xh  = (__half*)(scratch + O_XH);
    __half* xl  = (__half*)(scratch + O_XL);
    __half* byh = (__half*)(scratch + O_BYH);
    __half* byl = (__half*)(scratch + O_BYL);
    float*  seg = scratch + O_SEG;
    float*  cnt = scratch + O_CNT;
    float*  bz  = scratch + O_BZ;
    __half* qh  = (__half*)(scratch + O_QH);
    __half* ql  = (__half*)(scratch + O_QL);
    float*  loss = scratch + O_LOSS;
    __half* wh  = (__half*)(scratch + O_WH);
    __half* wl  = (__half*)(scratch + O_WL);

    const float* x        = (const float*)d_in[0];
    const float* in_mask  = (const float*)d_in[1];
    const int*   mel2ph   = (const int*)  d_in[2];
    const float* ph_mask  = (const float*)d_in[3];
    const float* conv_in_w = (const float*)d_in[4];
    const float* conv_in_b = (const float*)d_in[5];
    const float* enc_ln_g = (const float*)d_in[6];
    const float* enc_ln_b = (const float*)d_in[7];
    const float* enc_w1   = (const float*)d_in[8];
    const float* enc_b1   = (const float*)d_in[9];
    const float* enc_w2   = (const float*)d_in[10];
    const float* enc_b2   = (const float*)d_in[11];
    const float* enc_last_g = (const float*)d_in[12];
    const float* enc_last_b = (const float*)d_in[13];
    const float* enc_post_w = (const float*)d_in[14];
    const float* enc_post_b = (const float*)d_in[15];
    const float* pn_ln_g = (const float*)d_in[16];
    const float* pn_ln_b = (const float*)d_in[17];
    const float* pn_w1   = (const float*)d_in[18];
    const float* pn_b1   = (const float*)d_in[19];
    const float* pn_w2   = (const float*)d_in[20];
    const float* pn_b2   = (const float*)d_in[21];
    const float* pn_last_g = (const float*)d_in[22];
    const float* pn_last_b = (const float*)d_in[23];
    const float* pn_post_w = (const float*)d_in[24];
    const float* pn_post_b = (const float*)d_in[25];
    const float* proj_in_w  = (const float*)d_in[26];
    const float* proj_in_b  = (const float*)d_in[27];
    const float* proj_out_w = (const float*)d_in[28];
    const float* proj_out_b = (const float*)d_in[29];
    const float* codebook   = (const float*)d_in[30];

    float* out = (float*)d_out;
    const float scale = 0.57735026918962576f;   // 3^-0.5

    // smem bytes: A = 4*KS*768 u32, B = 4*1216 u32
    const int SM3 = (4 * 3 * 768 + 4 * 1216) * 4;   // 56320
    const int SM1 = (4 * 1 * 768 + 4 * 1216) * 4;   // 31744
    cudaFuncSetAttribute(mma_conv<3>, cudaFuncAttributeMaxDynamicSharedMemorySize, SM3);
    cudaFuncSetAttribute(mma_conv<1>, cudaFuncAttributeMaxDynamicSharedMemorySize, SM1);

    dim3 blk(256);

    // ---- prepass ----
    split_x<<<((int)SZ_X + 255) / 256, 256>>>(x, xh, xl, 80, TT, (int)SZ_X);
    prep_w<<<((int)WSZ_CIN + 255) / 256, 256>>>(conv_in_w, wh + OW_CIN, wl + OW_CIN,
                                                (int)WSZ_CIN, HH, 80, 1);
    prep_w<<<((int)WSZ_E1 + 255) / 256, 256>>>(enc_w1, wh + OW_E1, wl + OW_E1,
                                               (int)WSZ_E1, HH2, HH, 3);
    prep_w<<<((int)WSZ_E2 + 255) / 256, 256>>>(enc_w2, wh + OW_E2, wl + OW_E2,
                                               (int)WSZ_E2, HH, HH2, 1);
    prep_w<<<((int)WSZ_EP + 255) / 256, 256>>>(enc_post_w, wh + OW_EP, wl + OW_EP,
                                               (int)WSZ_EP, HH, HH, 3);
    prep_w<<<((int)WSZ_E1 + 255) / 256, 256>>>(pn_w1, wh + OW_P1, wl + OW_P1,
                                               (int)WSZ_E1, HH2, HH, 3);
    prep_w<<<((int)WSZ_E2 + 255) / 256, 256>>>(pn_w2, wh + OW_P2, wl + OW_P2,
                                               (int)WSZ_E2, HH, HH2, 1);
    prep_w<<<((int)WSZ_EP + 255) / 256, 256>>>(pn_post_w, wh + OW_PP, wl + OW_PP,
                                               (int)WSZ_EP, HH, HH, 3);
    prep_w<<<((int)WSZ_PI + 255) / 256, 256>>>(proj_in_w, wh + OW_PI, wl + OW_PI,
                                               (int)WSZ_PI, CVQd, HH, 1);
    prep_w<<<((int)WSZ_PO + 255) / 256, 256>>>(proj_out_w, wh + OW_PO, wl + OW_PO,
                                               (int)WSZ_PO, HH, CVQd, 1);

    // ---- encoder (T = TT) ----
    mma_conv<1><<<dim3(TT/128, HH/64, BB), blk, SM1>>>(xh, xl, wh + OW_CIN, wl + OW_CIN,
        conv_in_b, bx, nullptr, nullptr, nullptr, in_mask, 80, HH, TT, 1.f, 0);
    for (int i = 0; i < NLB; i++) {
        ln_kernel<<<(BB*TT + 255)/256, 256>>>(bx, bnh, bnl,
            enc_ln_g + i*HH, enc_ln_b + i*HH, nullptr, TT);
        mma_conv<3><<<dim3(TT/128, HH2/64, BB), blk, SM3>>>(bnh, bnl,
            wh + OW_E1 + (size_t)i*HH2*HH*3, wl + OW_E1 + (size_t)i*HH2*HH*3,
            enc_b1 + i*HH2, nullptr, bmh, bml, nullptr, nullptr, HH, HH2, TT, scale, 1);
        mma_conv<1><<<dim3(TT/128, HH/64, BB), blk, SM1>>>(bmh, bml,
            wh + OW_E2 + (size_t)i*HH*HH2, wl + OW_E2 + (size_t)i*HH*HH2,
            enc_b2 + i*HH, bx, nullptr, nullptr, bx, in_mask, HH2, HH, TT, 1.f, 0);
    }
    ln_kernel<<<(BB*TT + 255)/256, 256>>>(bx, bnh, bnl, enc_last_g, enc_last_b, in_mask, TT);
    mma_conv<3><<<dim3(TT/128, HH/64, BB), blk, SM3>>>(bnh, bnl, wh + OW_EP, wl + OW_EP,
        enc_post_b, by, nullptr, nullptr, nullptr, in_mask, HH, HH, TT, 1.f, 0);

    // ---- group by segments -> [B,H,L] into bx ----
    seg_zero<<<((int)SZ_SEG + 255)/256, 256>>>(seg, cnt);
    seg_scatter<<<dim3(TT, BB), HH>>>(by, mel2ph, seg, cnt);
    seg_div<<<(BB*HH*LL + 255)/256, 256>>>(seg, cnt, bx);

    // ---- postnet (T = LL) ----
    for (int i = 0; i < NLB; i++) {
        ln_kernel<<<(BB*LL + 255)/256, 256>>>(bx, bnh, bnl,
            pn_ln_g + i*HH, pn_ln_b + i*HH, nullptr, LL);
        mma_conv<3><<<dim3(LL/128, HH2/64, BB), blk, SM3>>>(bnh, bnl,
            wh + OW_P1 + (size_t)i*HH2*HH*3, wl + OW_P1 + (size_t)i*HH2*HH*3,
            pn_b1 + i*HH2, nullptr, bmh, bml, nullptr, nullptr, HH, HH2, LL, scale, 1);
        mma_conv<1><<<dim3(LL/128, HH/64, BB), blk, SM1>>>(bmh, bml,
            wh + OW_P2 + (size_t)i*HH*HH2, wl + OW_P2 + (size_t)i*HH*HH2,
            pn_b2 + i*HH, bx, nullptr, nullptr, bx, ph_mask, HH2, HH, LL, 1.f, 0);
    }
    ln_kernel<<<(BB*LL + 255)/256, 256>>>(bx, bnh, bnl, pn_last_g, pn_last_b, ph_mask, LL);
    mma_conv<3><<<dim3(LL/128, HH/64, BB), blk, SM3>>>(bnh, bnl, wh + OW_PP, wl + OW_PP,
        pn_post_b, nullptr, byh, byl, nullptr, ph_mask, HH, HH, LL, 1.f, 0);

    // ---- proj_in -> VQ -> proj_out ----
    mma_conv<1><<<dim3(LL/128, CVQd/64, BB), blk, SM1>>>(byh, byl, wh + OW_PI, wl + OW_PI,
        proj_in_b, bz, nullptr, nullptr, nullptr, nullptr, HH, CVQd, LL, 1.f, 0);
    loss_init<<<1, 32>>>(loss);
    vq_kernel<<<dim3(LL, BB), 128>>>(bz, codebook, qh, ql, out + (size_t)BB*HH*LL + 1, loss);
    mma_conv<1><<<dim3(LL/128, HH/64, BB), blk, SM1>>>(qh, ql, wh + OW_PO, wl + OW_PO,
        proj_out_b, out, nullptr, nullptr, nullptr, nullptr, CVQd, HH, LL, 1.f, 0);
    loss_fin<<<1, 1>>>(loss, out + (size_t)BB*HH*LL);
}

// round 8
// speedup vs baseline: 3.2049x; 1.0491x over previous
#include <cuda_runtime.h>
#include <cuda_fp16.h>
#include <math.h>
#include <stdint.h>

// ---------------- problem constants ----------------
#define BB   16
#define TT   2048
#define LL   512
#define HH   256
#define HH2  512
#define CVQd 64
#define NLB  10   // NL * NB

// ---------------- sizes (floats) ----------------
#define SZ_BHT  ((size_t)BB*HH*TT)
#define SZ_BMT  ((size_t)BB*HH2*TT)
#define SZ_X    ((size_t)BB*80*TT)
#define SZ_BHL  ((size_t)BB*HH*LL)
#define SZ_SEG  ((size_t)BB*HH*(LL+1))
#define SZ_CNT  ((size_t)BB*(LL+1))
#define SZ_BZL  ((size_t)BB*CVQd*LL)

// weight plane sizes (elements)
#define WSZ_CIN ((size_t)HH*80)
#define WSZ_E1  ((size_t)NLB*HH2*HH*3)
#define WSZ_E2  ((size_t)NLB*HH*HH2)
#define WSZ_EP  ((size_t)HH*HH*3)
#define WSZ_PI  ((size_t)CVQd*HH)
#define WSZ_PO  ((size_t)HH*CVQd)
#define WTOT    (WSZ_CIN + 2*(WSZ_E1 + WSZ_E2 + WSZ_EP) + WSZ_PI + WSZ_PO)

// scratch offsets (float units). half planes take size/2 floats.
// ALL activation tensors are t-major: [b][t][c].
#define O_BX   ((size_t)0)
#define O_BY   (O_BX  + SZ_BHT)
#define O_BNH  (O_BY  + SZ_BHT)
#define O_BNL  (O_BNH + SZ_BHT/2)
#define O_BMH  (O_BNL + SZ_BHT/2)
#define O_BML  (O_BMH + SZ_BMT/2)
#define O_XH   (O_BML + SZ_BMT/2)
#define O_XL   (O_XH  + SZ_X/2)
#define O_BYH  (O_XL  + SZ_X/2)
#define O_BYL  (O_BYH + SZ_BHL/2)
#define O_SEG  (O_BYL + SZ_BHL/2)
#define O_CNT  (O_SEG + SZ_SEG)
#define O_BZ   (O_CNT + SZ_CNT)
#define O_QH   (O_BZ  + SZ_BZL)
#define O_QL   (O_QH  + SZ_BZL/2)
#define O_LOSS (O_QL  + SZ_BZL/2)
#define O_WH   (O_LOSS + 16)
#define O_WL   (O_WH  + WTOT/2)
#define SCRATCH_TOT (O_WL + WTOT/2)

__device__ __align__(16) float g_scratch[SCRATCH_TOT];

// weight offsets inside wh/wl planes (element units)
#define OW_CIN ((size_t)0)
#define OW_E1  (OW_CIN + WSZ_CIN)
#define OW_E2  (OW_E1 + WSZ_E1)
#define OW_EP  (OW_E2 + WSZ_E2)
#define OW_P1  (OW_EP + WSZ_EP)
#define OW_P2  (OW_P1 + WSZ_E1)
#define OW_PP  (OW_P2 + WSZ_E2)
#define OW_PI  (OW_PP + WSZ_EP)
#define OW_PO  (OW_PI + WSZ_PI)

// ---------------- helpers ----------------
__device__ __forceinline__ uint32_t smem_to_u32(const void* p) {
    uint32_t a;
    asm("{ .reg .u64 t; cvta.to.shared.u64 t, %1; cvt.u32.u64 %0, t; }" : "=r"(a) : "l"(p));
    return a;
}
#define CP16(dst, src) \
    asm volatile("cp.async.cg.shared.global [%0], [%1], 16;" :: "r"(dst), "l"(src))
#define CP16Z(dst, src, ssz) \
    asm volatile("cp.async.cg.shared.global [%0], [%1], 16, %2;" :: "r"(dst), "l"(src), "r"(ssz))

#define LDSM4(r0, r1, r2, r3, addr)                                              \
    asm volatile("ldmatrix.sync.aligned.m8n8.x4.shared.b16 {%0,%1,%2,%3}, [%4];" \
        : "=r"(r0), "=r"(r1), "=r"(r2), "=r"(r3) : "r"(addr))

#define MMA_F16(C, A, B)                                                         \
    asm volatile("mma.sync.aligned.m16n8k16.row.col.f32.f16.f16.f32 "            \
        "{%0,%1,%2,%3}, {%4,%5,%6,%7}, {%8,%9}, {%0,%1,%2,%3};"                  \
        : "+f"((C)[0]), "+f"((C)[1]), "+f"((C)[2]), "+f"((C)[3])                  \
        : "r"((A)[0]), "r"((A)[1]), "r"((A)[2]), "r"((A)[3]),                     \
          "r"((B)[0]), "r"((B)[1]))

__device__ __forceinline__ void split_f16(float v, __half& h, __half& l)
{
    h = __float2half_rn(v);
    l = __float2half_rn(v - __half2float(h));
}

// ---------------- prepass: x [b][c][t] -> t-major fp16 hi/lo [b][t][c] ----------------
__global__ void split_x(const float* __restrict__ s, __half* __restrict__ dh,
                        __half* __restrict__ dl, int C, int Tdim, int n)
{
    int i = blockIdx.x * blockDim.x + threadIdx.x;
    if (i >= n) return;
    int b = i / (C * Tdim);
    int r = i - b * C * Tdim;
    int c = r / Tdim, t = r - c * Tdim;
    __half h, l;
    split_f16(s[i], h, l);
    size_t o = ((size_t)b * Tdim + t) * C + c;
    dh[o] = h; dl[o] = l;
}

// ---------------- prepass: weights -> pre-tiled fp16 hi/lo ----------------
// src [layer][co][ci][tap] -> dst [layer][co][(ci>>4)*16KS + tap*16 + (ci&15)]
__global__ void prep_w(const float* __restrict__ w, __half* __restrict__ oh,
                       __half* __restrict__ ol, int total, int Cout, int Cin, int KS)
{
    int idx = blockIdx.x * blockDim.x + threadIdx.x;
    if (idx >= total) return;
    int per_layer = Cout * Cin * KS;
    int layer = idx / per_layer;
    int r = idx - layer * per_layer;
    int co = r / (Cin * KS);
    int r2 = r - co * (Cin * KS);
    int ci = r2 / KS;
    int tap = r2 - ci * KS;
    __half h, l;
    split_f16(w[idx], h, l);
    int kidx = (ci >> 4) * (16 * KS) + tap * 16 + (ci & 15);
    size_t o = ((size_t)layer * Cout + co) * (size_t)(Cin * KS) + kidx;
    oh[o] = h; ol[o] = l;
}

// ---------------- LayerNorm (t-major): warp per row ----------------
__global__ void ln_kernel(const float* __restrict__ in, __half* __restrict__ outh,
                          __half* __restrict__ outl,
                          const float* __restrict__ gma, const float* __restrict__ bta,
                          const float* __restrict__ mask, int Tdim)
{
    int row = blockIdx.x * 8 + (threadIdx.x >> 5);
    if (row >= BB * Tdim) return;
    int lane = threadIdx.x & 31;
    const float4* p = (const float4*)(in + (size_t)row * HH) + lane * 2;
    float4 a = p[0], q = p[1];
    float v[8] = {a.x, a.y, a.z, a.w, q.x, q.y, q.z, q.w};
    float s = 0.f, s2 = 0.f;
    #pragma unroll
    for (int i = 0; i < 8; i++) { s += v[i]; s2 += v[i] * v[i]; }
    #pragma unroll
    for (int o = 16; o; o >>= 1) {
        s  += __shfl_xor_sync(0xffffffffu, s, o);
        s2 += __shfl_xor_sync(0xffffffffu, s2, o);
    }
    float mean = s * (1.f / HH);
    float var  = s2 * (1.f / HH) - mean * mean;
    float r = rsqrtf(var + 1e-5f);
    float mk = mask ? mask[row] : 1.f;
    __half2 hv[4], lv[4];
    #pragma unroll
    for (int i = 0; i < 4; i++) {
        int c = lane * 8 + 2 * i;
        float n0 = ((v[2*i]   - mean) * r * gma[c]     + bta[c])     * mk;
        float n1 = ((v[2*i+1] - mean) * r * gma[c + 1] + bta[c + 1]) * mk;
        __half h0, l0, h1, l1;
        split_f16(n0, h0, l0);
        split_f16(n1, h1, l1);
        hv[i] = __halves2half2(h0, h1);
        lv[i] = __halves2half2(l0, l1);
    }
    *(uint4*)(outh + (size_t)row * HH + lane * 8) = *(uint4*)hv;
    *(uint4*)(outl + (size_t)row * HH + lane * 8) = *(uint4*)lv;
}

// ---------------- fp16-split mma.sync conv GEMM, all-cp.async + ldmatrix ----------------
// D[co 64][t 128]; activations t-major [b][t][c]; weights pre-tiled [co][k].
// KS=3: stage = 16 ci (3 k16-steps, taps folded into k). KS=1: stage = 32 ci (2 k16-steps).
template<int KS>
__global__ void __launch_bounds__(256)
mma_conv(const __half* __restrict__ inh, const __half* __restrict__ inl,
         const __half* __restrict__ wh, const __half* __restrict__ wl,
         const float* __restrict__ bias,
         float* outF, int tmaj, __half* outH, __half* outL,
         const float* __restrict__ residual, const float* __restrict__ mask,
         int Cin, int Cout, int Tdim, float scale, int dogelu)
{
    extern __shared__ char smc[];
    constexpr int SX = (KS == 3) ? 56 : 40;   // halves per X/W row (padded)
    constexpr int XPL = 128 * SX;             // halves per X plane
    constexpr int WPL = 64 * SX;
    constexpr int BUF = 2 * (XPL + WPL);      // halves per buffer (Xh,Xl,Wh,Wl)

    const int b   = blockIdx.z;
    const int cog = blockIdx.y * 64;
    const int tg  = blockIdx.x * 128;
    const int tid = threadIdx.x;
    const int lane = tid & 31, wid = tid >> 5;
    const int wm = wid >> 2, wn = wid & 3;
    const int g = lane >> 2, th = lane & 3;

    const uint32_t smb = smem_to_u32(smc);
    const int Ktot = Cin * KS;
    const size_t xb = (size_t)b * Tdim * Cin;   // halves

    // ldmatrix per-lane offsets (halves)
    const int laneA = ((lane & 7) + ((lane >> 3) & 1) * 8) * SX + (lane >> 4) * 8;
    const int laneB = ((lane & 7) + (lane >> 4) * 8) * SX + ((lane >> 3) & 1) * 8;

    float c[2][4][4];
    #pragma unroll
    for (int i = 0; i < 2; i++)
        #pragma unroll
        for (int j = 0; j < 4; j++)
            #pragma unroll
            for (int k = 0; k < 4; k++) c[i][j][k] = 0.f;

    const int nst = (KS == 3) ? (Cin >> 4) : ((Cin + 31) >> 5);

    auto load_stage = [&](int s, int buf) {
        const uint32_t bb = smb + 2u * (uint32_t)(buf * BUF);
        if (KS == 3) {
            const int ci0 = s * 16, kbase = ci0 * 3;
            // W: 2 planes x 64 rows x 6 chunks
            for (int ic = tid; ic < 768; ic += 256) {
                int plane = ic / 384, r = ic - plane * 384;
                int row = r / 6, ch = r - row * 6;
                const __half* src = (plane ? wl : wh) + (size_t)(cog + row) * Ktot + kbase + ch * 8;
                CP16(bb + 2u * (uint32_t)(2 * XPL + plane * WPL + row * SX + ch * 8), src);
            }
            // X: 2 planes x 128 t x 3 taps x 2 chunks
            for (int ic = tid; ic < 1536; ic += 256) {
                int plane = ic / 768, r = ic - plane * 768;
                int t = r / 6, q = r - t * 6;
                int tap = q >> 1, ch = q & 1;
                int gt = tg + t + tap - 2;
                const __half* src = (plane ? inl : inh) + xb + (size_t)gt * Cin + ci0 + ch * 8;
                int ssz = (gt >= 0) ? 16 : 0;
                CP16Z(bb + 2u * (uint32_t)(plane * XPL + t * SX + tap * 16 + ch * 8), src, ssz);
            }
        } else {
            const int ci0 = s * 32;
            const int steps = ((Cin - ci0) >= 32) ? 2 : 1;
            const int cw = steps * 2;
            for (int ic = tid; ic < 2 * 64 * cw; ic += 256) {
                int plane = ic / (64 * cw), r = ic - plane * (64 * cw);
                int row = r / cw, ch = r - row * cw;
                const __half* src = (plane ? wl : wh) + (size_t)(cog + row) * Ktot + ci0 + ch * 8;
                CP16(bb + 2u * (uint32_t)(2 * XPL + plane * WPL + row * SX + ch * 8), src);
            }
            for (int ic = tid; ic < 2 * 128 * cw; ic += 256) {
                int plane = ic / (128 * cw), r = ic - plane * (128 * cw);
                int t = r / cw, ch = r - t * cw;
                const __half* src = (plane ? inl : inh) + xb + (size_t)(tg + t) * Cin + ci0 + ch * 8;
                CP16(bb + 2u * (uint32_t)(plane * XPL + t * SX + ch * 8), src);
            }
        }
    };

    auto compute = [&](int buf, int ksteps) {
        const uint32_t bb = smb + 2u * (uint32_t)(buf * BUF);
        for (int ks = 0; ks < ksteps; ks++) {
            uint32_t ah[2][4], al[2][4], bh[4][2], bl[4][2];
            #pragma unroll
            for (int mf = 0; mf < 2; mf++) {
                uint32_t base = bb + 2u * (uint32_t)(2 * XPL + (wm * 32 + mf * 16) * SX + ks * 16 + laneA);
                LDSM4(ah[mf][0], ah[mf][1], ah[mf][2], ah[mf][3], base);
                LDSM4(al[mf][0], al[mf][1], al[mf][2], al[mf][3], base + 2u * (uint32_t)WPL);
            }
            #pragma unroll
            for (int p = 0; p < 2; p++) {
                uint32_t base = bb + 2u * (uint32_t)((wn * 32 + p * 16) * SX + ks * 16 + laneB);
                LDSM4(bh[2*p][0], bh[2*p][1], bh[2*p+1][0], bh[2*p+1][1], base);
                LDSM4(bl[2*p][0], bl[2*p][1], bl[2*p+1][0], bl[2*p+1][1], base + 2u * (uint32_t)XPL);
            }
            #pragma unroll
            for (int mf = 0; mf < 2; mf++)
                #pragma unroll
                for (int nf = 0; nf < 4; nf++) {
                    MMA_F16(c[mf][nf], ah[mf], bh[nf]);
                    MMA_F16(c[mf][nf], ah[mf], bl[nf]);
                    MMA_F16(c[mf][nf], al[mf], bh[nf]);
                }
        }
    };

    load_stage(0, 0);
    asm volatile("cp.async.commit_group;");
    for (int s = 0; s < nst; s++) {
        int buf = s & 1;
        bool more = (s + 1 < nst);
        if (more) {
            load_stage(s + 1, buf ^ 1);
            asm volatile("cp.async.commit_group;");
            asm volatile("cp.async.wait_group 1;");
        } else {
            asm volatile("cp.async.wait_group 0;");
        }
        __syncthreads();
        int ksteps = (KS == 3) ? 3 : (((Cin - s * 32) >= 32) ? 2 : 1);
        compute(buf, ksteps);
        __syncthreads();
    }

    // ---- epilogue ----
    #pragma unroll
    for (int mf = 0; mf < 2; mf++) {
        #pragma unroll
        for (int nf = 0; nf < 4; nf++) {
            int co0 = cog + wm * 32 + mf * 16 + g;
            int t0 = tg + wn * 32 + nf * 8 + 2 * th;
            float mk0 = mask ? mask[b * Tdim + t0] : 1.f;
            float mk1 = mask ? mask[b * Tdim + t0 + 1] : 1.f;
            #pragma unroll
            for (int half = 0; half < 2; half++) {
                int co = co0 + half * 8;
                float bi = bias[co];
                float v0 = (c[mf][nf][half * 2 + 0] + bi) * scale;
                float v1 = (c[mf][nf][half * 2 + 1] + bi) * scale;
                if (dogelu) {
                    v0 = 0.5f * v0 * (1.f + erff(v0 * 0.70710678118654752f));
                    v1 = 0.5f * v1 * (1.f + erff(v1 * 0.70710678118654752f));
                }
                size_t r0 = ((size_t)b * Tdim + t0) * Cout + co;
                size_t r1 = r0 + Cout;
                if (residual) { v0 += residual[r0]; v1 += residual[r1]; }
                if (mask) { v0 *= mk0; v1 *= mk1; }
                if (outF) {
                    if (tmaj) { outF[r0] = v0; outF[r1] = v1; }
                    else {
                        size_t o = ((size_t)b * Cout + co) * Tdim + t0;
                        outF[o] = v0; outF[o + 1] = v1;
                    }
                }
                if (outH) {
                    __half h0, l0, h1, l1;
                    split_f16(v0, h0, l0);
                    split_f16(v1, h1, l1);
                    outH[r0] = h0; outH[r1] = h1;
                    outL[r0] = l0; outL[r1] = l1;
                }
            }
        }
    }
}

// ---------------- group_by_segs (t-major) ----------------
__global__ void seg_zero(float* seg, float* cnt)
{
    int i = blockIdx.x * blockDim.x + threadIdx.x;
    if (i < (int)SZ_SEG) seg[i] = 0.f;
    if (i < (int)SZ_CNT) cnt[i] = 0.f;
}
__global__ void seg_scatter(const float* __restrict__ in, const int* __restrict__ mel2ph,
                            float* seg, float* cnt)
{
    int t = blockIdx.x, b = blockIdx.y, c = threadIdx.x;
    int ph = mel2ph[b * TT + t];
    if (ph < 1 || ph > LL) return;
    float v = in[((size_t)b * TT + t) * HH + c];
    atomicAdd(&seg[((size_t)b * (LL + 1) + ph) * HH + c], v);
    if (c == 0) atomicAdd(&cnt[b * (LL + 1) + ph], 1.f);
}
__global__ void seg_div(const float* __restrict__ seg, const float* __restrict__ cnt,
                        float* __restrict__ outg)
{
    int i = blockIdx.x * blockDim.x + threadIdx.x;   // over [b][l][c]
    if (i >= BB * LL * HH) return;
    int c = i % HH; int bl = i / HH; int l = bl % LL; int b = bl / LL;
    float s = seg[((size_t)b * (LL + 1) + l + 1) * HH + c];
    float n = fmaxf(cnt[b * (LL + 1) + l + 1], 1.f);
    outg[i] = s / n;
}

// ---------------- VQ (t-major) ----------------
__global__ void loss_init(float* loss) { if (threadIdx.x == 0) *loss = 0.f; }

__global__ void vq_kernel(const float* __restrict__ z, const float* __restrict__ cb,
                          __half* __restrict__ qh, __half* __restrict__ ql,
                          float* __restrict__ outIdx, float* loss)
{
    __shared__ float zsh[64];
    __shared__ float dsh[128];
    __shared__ int   ish[128];
    int l = blockIdx.x, b = blockIdx.y, tid = threadIdx.x;
    if (tid < 64) zsh[tid] = z[((size_t)b * LL + l) * CVQd + tid];
    __syncthreads();
    float x2 = 0.f, dot = 0.f, c2 = 0.f;
    #pragma unroll 8
    for (int c = 0; c < 64; c++) {
        float zv = zsh[c]; float cv = cb[tid * 64 + c];
        x2 += zv * zv; dot += zv * cv; c2 += cv * cv;
    }
    dsh[tid] = x2 - 2.f * dot + c2;
    ish[tid] = tid;
    __syncthreads();
    for (int s = 64; s > 0; s >>= 1) {
        if (tid < s) {
            float d2 = dsh[tid + s]; int i2 = ish[tid + s];
            if (d2 < dsh[tid] || (d2 == dsh[tid] && i2 < ish[tid])) { dsh[tid] = d2; ish[tid] = i2; }
        }
        __syncthreads();
    }
    int best = ish[0];
    __syncthreads();
    float part = 0.f;
    if (tid < 64) {
        float qv = cb[best * 64 + tid];
        size_t oi = ((size_t)b * LL + l) * CVQd + tid;
        __half h, lo;
        split_f16(qv, h, lo);
        qh[oi] = h; ql[oi] = lo;
        float dd = zsh[tid] - qv;
        part = dd * dd;
    }
    dsh[tid] = part;
    __syncthreads();
    for (int s = 64; s > 0; s >>= 1) { if (tid < s) dsh[tid] += dsh[tid + s]; __syncthreads(); }
    if (tid == 0) {
        atomicAdd(loss, dsh[0]);
        outIdx[b * LL + l] = (float)best;
    }
}

__global__ void loss_fin(const float* loss, float* out)
{
    out[0] = loss[0] * 0.25f / (float)(BB * LL * CVQd);
}

// ---------------- launch ----------------
extern "C" void kernel_launch(void* const* d_in, const int* in_sizes, int n_in,
                              void* d_out, int out_size)
{
    float* scratch = nullptr;
    cudaGetSymbolAddress((void**)&scratch, g_scratch);
    float*  bx  = scratch + O_BX;
    float*  by  = scratch + O_BY;
    __half* bnh = (__half*)(scratch + O_BNH);
    __half* bnl = (__half*)(scratch + O_BNL);
    __half* bmh = (__half*)(scratch + O_BMH);
    __half* bml = (__half*)(scratch + O_BML);
    __half* xh  = (__half*)(scratch + O_XH);
    __half* xl  = (__half*)(scratch + O_XL);
    __half* byh = (__half*)(scratch + O_BYH);
    __half* byl = (__half*)(scratch + O_BYL);
    float*  seg = scratch + O_SEG;
    float*  cnt = scratch + O_CNT;
    float*  bz  = scratch + O_BZ;
    __half* qh  = (__half*)(scratch + O_QH);
    __half* ql  = (__half*)(scratch + O_QL);
    float*  loss = scratch + O_LOSS;
    __half* wh  = (__half*)(scratch + O_WH);
    __half* wl  = (__half*)(scratch + O_WL);

    const float* x        = (const float*)d_in[0];
    const float* in_mask  = (const float*)d_in[1];
    const int*   mel2ph   = (const int*)  d_in[2];
    const float* ph_mask  = (const float*)d_in[3];
    const float* conv_in_w = (const float*)d_in[4];
    const float* conv_in_b = (const float*)d_in[5];
    const float* enc_ln_g = (const float*)d_in[6];
    const float* enc_ln_b = (const float*)d_in[7];
    const float* enc_w1   = (const float*)d_in[8];
    const float* enc_b1   = (const float*)d_in[9];
    const float* enc_w2   = (const float*)d_in[10];
    const float* enc_b2   = (const float*)d_in[11];
    const float* enc_last_g = (const float*)d_in[12];
    const float* enc_last_b = (const float*)d_in[13];
    const float* enc_post_w = (const float*)d_in[14];
    const float* enc_post_b = (const float*)d_in[15];
    const float* pn_ln_g = (const float*)d_in[16];
    const float* pn_ln_b = (const float*)d_in[17];
    const float* pn_w1   = (const float*)d_in[18];
    const float* pn_b1   = (const float*)d_in[19];
    const float* pn_w2   = (const float*)d_in[20];
    const float* pn_b2   = (const float*)d_in[21];
    const float* pn_last_g = (const float*)d_in[22];
    const float* pn_last_b = (const float*)d_in[23];
    const float* pn_post_w = (const float*)d_in[24];
    const float* pn_post_b = (const float*)d_in[25];
    const float* proj_in_w  = (const float*)d_in[26];
    const float* proj_in_b  = (const float*)d_in[27];
    const float* proj_out_w = (const float*)d_in[28];
    const float* proj_out_b = (const float*)d_in[29];
    const float* codebook   = (const float*)d_in[30];

    float* out = (float*)d_out;
    const float scale = 0.57735026918962576f;   // 3^-0.5

    // smem: KS=3: 2 buf * 2*(128*56 + 64*56) halves * 2B = 86016 B
    //       KS=1: 2 buf * 2*(128*40 + 64*40) halves * 2B = 61440 B
    const int SM3 = 2 * 2 * (128 * 56 + 64 * 56) * 2;
    const int SM1 = 2 * 2 * (128 * 40 + 64 * 40) * 2;
    cudaFuncSetAttribute(mma_conv<3>, cudaFuncAttributeMaxDynamicSharedMemorySize, SM3);
    cudaFuncSetAttribute(mma_conv<1>, cudaFuncAttributeMaxDynamicSharedMemorySize, SM1);

    dim3 blk(256);

    // ---- prepass ----
    split_x<<<((int)SZ_X + 255) / 256, 256>>>(x, xh, xl, 80, TT, (int)SZ_X);
    prep_w<<<((int)WSZ_CIN + 255) / 256, 256>>>(conv_in_w, wh + OW_CIN, wl + OW_CIN,
                                                (int)WSZ_CIN, HH, 80, 1);
    prep_w<<<((int)WSZ_E1 + 255) / 256, 256>>>(enc_w1, wh + OW_E1, wl + OW_E1,
                                               (int)WSZ_E1, HH2, HH, 3);
    prep_w<<<((int)WSZ_E2 + 255) / 256, 256>>>(enc_w2, wh + OW_E2, wl + OW_E2,
                                               (int)WSZ_E2, HH, HH2, 1);
    prep_w<<<((int)WSZ_EP + 255) / 256, 256>>>(enc_post_w, wh + OW_EP, wl + OW_EP,
                                               (int)WSZ_EP, HH, HH, 3);
    prep_w<<<((int)WSZ_E1 + 255) / 256, 256>>>(pn_w1, wh + OW_P1, wl + OW_P1,
                                               (int)WSZ_E1, HH2, HH, 3);
    prep_w<<<((int)WSZ_E2 + 255) / 256, 256>>>(pn_w2, wh + OW_P2, wl + OW_P2,
                                               (int)WSZ_E2, HH, HH2, 1);
    prep_w<<<((int)WSZ_EP + 255) / 256, 256>>>(pn_post_w, wh + OW_PP, wl + OW_PP,
                                               (int)WSZ_EP, HH, HH, 3);
    prep_w<<<((int)WSZ_PI + 255) / 256, 256>>>(proj_in_w, wh + OW_PI, wl + OW_PI,
                                               (int)WSZ_PI, CVQd, HH, 1);
    prep_w<<<((int)WSZ_PO + 255) / 256, 256>>>(proj_out_w, wh + OW_PO, wl + OW_PO,
                                               (int)WSZ_PO, HH, CVQd, 1);

    // ---- encoder (T = TT) ----
    mma_conv<1><<<dim3(TT/128, HH/64, BB), blk, SM1>>>(xh, xl, wh + OW_CIN, wl + OW_CIN,
        conv_in_b, bx, 1, nullptr, nullptr, nullptr, in_mask, 80, HH, TT, 1.f, 0);
    for (int i = 0; i < NLB; i++) {
        ln_kernel<<<(BB*TT)/8, 256>>>(bx, bnh, bnl,
            enc_ln_g + i*HH, enc_ln_b + i*HH, nullptr, TT);
        mma_conv<3><<<dim3(TT/128, HH2/64, BB), blk, SM3>>>(bnh, bnl,
            wh + OW_E1 + (size_t)i*HH2*HH*3, wl + OW_E1 + (size_t)i*HH2*HH*3,
            enc_b1 + i*HH2, nullptr, 0, bmh, bml, nullptr, nullptr, HH, HH2, TT, scale, 1);
        mma_conv<1><<<dim3(TT/128, HH/64, BB), blk, SM1>>>(bmh, bml,
            wh + OW_E2 + (size_t)i*HH*HH2, wl + OW_E2 + (size_t)i*HH*HH2,
            enc_b2 + i*HH, bx, 1, nullptr, nullptr, bx, in_mask, HH2, HH, TT, 1.f, 0);
    }
    ln_kernel<<<(BB*TT)/8, 256>>>(bx, bnh, bnl, enc_last_g, enc_last_b, in_mask, TT);
    mma_conv<3><<<dim3(TT/128, HH/64, BB), blk, SM3>>>(bnh, bnl, wh + OW_EP, wl + OW_EP,
        enc_post_b, by, 1, nullptr, nullptr, nullptr, in_mask, HH, HH, TT, 1.f, 0);

    // ---- group by segments -> [b][l][c] into bx ----
    seg_zero<<<((int)SZ_SEG + 255)/256, 256>>>(seg, cnt);
    seg_scatter<<<dim3(TT, BB), HH>>>(by, mel2ph, seg, cnt);
    seg_div<<<(BB*LL*HH + 255)/256, 256>>>(seg, cnt, bx);

    // ---- postnet (T = LL) ----
    for (int i = 0; i < NLB; i++) {
        ln_kernel<<<(BB*LL)/8, 256>>>(bx, bnh, bnl,
            pn_ln_g + i*HH, pn_ln_b + i*HH, nullptr, LL);
        mma_conv<3><<<dim3(LL/128, HH2/64, BB), blk, SM3>>>(bnh, bnl,
            wh + OW_P1 + (size_t)i*HH2*HH*3, wl + OW_P1 + (size_t)i*HH2*HH*3,
            pn_b1 + i*HH2, nullptr, 0, bmh, bml, nullptr, nullptr, HH, HH2, LL, scale, 1);
        mma_conv<1><<<dim3(LL/128, HH/64, BB), blk, SM1>>>(bmh, bml,
            wh + OW_P2 + (size_t)i*HH*HH2, wl + OW_P2 + (size_t)i*HH*HH2,
            pn_b2 + i*HH, bx, 1, nullptr, nullptr, bx, ph_mask, HH2, HH, LL, 1.f, 0);
    }
    ln_kernel<<<(BB*LL)/8, 256>>>(bx, bnh, bnl, pn_last_g, pn_last_b, ph_mask, LL);
    mma_conv<3><<<dim3(LL/128, HH/64, BB), blk, SM3>>>(bnh, bnl, wh + OW_PP, wl + OW_PP,
        pn_post_b, nullptr, 0, byh, byl, nullptr, ph_mask, HH, HH, LL, 1.f, 0);

    // ---- proj_in -> VQ -> proj_out ----
    mma_conv<1><<<dim3(LL/128, 1, BB), blk, SM1>>>(byh, byl, wh + OW_PI, wl + OW_PI,
        proj_in_b, bz, 1, nullptr, nullptr, nullptr, nullptr, HH, CVQd, LL, 1.f, 0);
    loss_init<<<1, 32>>>(loss);
    vq_kernel<<<dim3(LL, BB), 128>>>(bz, codebook, qh, ql, out + (size_t)BB*HH*LL + 1, loss);
    mma_conv<1><<<dim3(LL/128, HH/64, BB), blk, SM1>>>(qh, ql, wh + OW_PO, wl + OW_PO,
        proj_out_b, out, 0, nullptr, nullptr, nullptr, nullptr, CVQd, HH, LL, 1.f, 0);
    loss_fin<<<1, 1>>>(loss, out + (size_t)BB*HH*LL);
}

// round 9
// speedup vs baseline: 3.5539x; 1.1089x over previous
#include <cuda_runtime.h>
#include <cuda_fp16.h>
#include <math.h>
#include <stdint.h>

// ---------------- problem constants ----------------
#define BB   16
#define TT   2048
#define LL   512
#define HH   256
#define HH2  512
#define CVQd 64
#define NLB  10   // NL * NB

// ---------------- sizes (floats) ----------------
#define SZ_BHT  ((size_t)BB*HH*TT)
#define SZ_BMT  ((size_t)BB*HH2*TT)
#define SZ_X    ((size_t)BB*80*TT)
#define SZ_BHL  ((size_t)BB*HH*LL)
#define SZ_SEG  ((size_t)BB*HH*(LL+1))
#define SZ_CNT  ((size_t)BB*(LL+1))
#define SZ_BZL  ((size_t)BB*CVQd*LL)

// weight plane sizes (elements)
#define WSZ_CIN ((size_t)HH*80)
#define WSZ_E1  ((size_t)NLB*HH2*HH*3)
#define WSZ_E2  ((size_t)NLB*HH*HH2)
#define WSZ_EP  ((size_t)HH*HH*3)
#define WSZ_PI  ((size_t)CVQd*HH)
#define WSZ_PO  ((size_t)HH*CVQd)
#define WTOT    (WSZ_CIN + 2*(WSZ_E1 + WSZ_E2 + WSZ_EP) + WSZ_PI + WSZ_PO)

// scratch offsets (float units). half planes take size/2 floats.
// ALL activation tensors are t-major: [b][t][c].
#define O_BX   ((size_t)0)
#define O_BY   (O_BX  + SZ_BHT)
#define O_BNH  (O_BY  + SZ_BHT)
#define O_BNL  (O_BNH + SZ_BHT/2)
#define O_BMH  (O_BNL + SZ_BHT/2)
#define O_BML  (O_BMH + SZ_BMT/2)
#define O_XH   (O_BML + SZ_BMT/2)
#define O_XL   (O_XH  + SZ_X/2)
#define O_BYH  (O_XL  + SZ_X/2)
#define O_BYL  (O_BYH + SZ_BHL/2)
#define O_SEG  (O_BYL + SZ_BHL/2)
#define O_CNT  (O_SEG + SZ_SEG)
#define O_BZ   (O_CNT + SZ_CNT)
#define O_QH   (O_BZ  + SZ_BZL)
#define O_QL   (O_QH  + SZ_BZL/2)
#define O_LOSS (O_QL  + SZ_BZL/2)
#define O_WH   (O_LOSS + 16)
#define O_WL   (O_WH  + WTOT/2)
#define SCRATCH_TOT (O_WL + WTOT/2)

__device__ __align__(16) float g_scratch[SCRATCH_TOT];

// weight offsets inside wh/wl planes (element units)
#define OW_CIN ((size_t)0)
#define OW_E1  (OW_CIN + WSZ_CIN)
#define OW_E2  (OW_E1 + WSZ_E1)
#define OW_EP  (OW_E2 + WSZ_E2)
#define OW_P1  (OW_EP + WSZ_EP)
#define OW_P2  (OW_P1 + WSZ_E1)
#define OW_PP  (OW_P2 + WSZ_E2)
#define OW_PI  (OW_PP + WSZ_EP)
#define OW_PO  (OW_PI + WSZ_PI)

// ---------------- helpers ----------------
__device__ __forceinline__ uint32_t smem_to_u32(const void* p) {
    uint32_t a;
    asm("{ .reg .u64 t; cvta.to.shared.u64 t, %1; cvt.u32.u64 %0, t; }" : "=r"(a) : "l"(p));
    return a;
}
#define CP16(dst, src) \
    asm volatile("cp.async.cg.shared.global [%0], [%1], 16;" :: "r"(dst), "l"(src))
#define CP16Z(dst, src, ssz) \
    asm volatile("cp.async.cg.shared.global [%0], [%1], 16, %2;" :: "r"(dst), "l"(src), "r"(ssz))

#define LDSM4(r0, r1, r2, r3, addr)                                              \
    asm volatile("ldmatrix.sync.aligned.m8n8.x4.shared.b16 {%0,%1,%2,%3}, [%4];" \
        : "=r"(r0), "=r"(r1), "=r"(r2), "=r"(r3) : "r"(addr))

#define MMA_F16(C, A, B)                                                         \
    asm volatile("mma.sync.aligned.m16n8k16.row.col.f32.f16.f16.f32 "            \
        "{%0,%1,%2,%3}, {%4,%5,%6,%7}, {%8,%9}, {%0,%1,%2,%3};"                  \
        : "+f"((C)[0]), "+f"((C)[1]), "+f"((C)[2]), "+f"((C)[3])                  \
        : "r"((A)[0]), "r"((A)[1]), "r"((A)[2]), "r"((A)[3]),                     \
          "r"((B)[0]), "r"((B)[1]))

__device__ __forceinline__ void split_f16(float v, __half& h, __half& l)
{
    h = __float2half_rn(v);
    l = __float2half_rn(v - __half2float(h));
}

// ---------------- merged prepass ----------------
__device__ __forceinline__ void prep_one(const float* __restrict__ w,
                                         __half* __restrict__ oh, __half* __restrict__ ol,
                                         int total, int Cout, int Cin, int KS, int idx)
{
    if (idx >= total) return;
    int per_layer = Cout * Cin * KS;
    int layer = idx / per_layer;
    int r = idx - layer * per_layer;
    int co = r / (Cin * KS);
    int r2 = r - co * (Cin * KS);
    int ci = r2 / KS;
    int tap = r2 - ci * KS;
    __half h, l;
    split_f16(w[idx], h, l);
    int kidx = (ci >> 4) * (16 * KS) + tap * 16 + (ci & 15);
    size_t o = ((size_t)layer * Cout + co) * (size_t)(Cin * KS) + kidx;
    oh[o] = h; ol[o] = l;
}

__global__ void prep_all(
    const float* __restrict__ x,
    const float* __restrict__ cinw, const float* __restrict__ e1,
    const float* __restrict__ e2,  const float* __restrict__ ep,
    const float* __restrict__ p1,  const float* __restrict__ p2,
    const float* __restrict__ pp,  const float* __restrict__ pi,
    const float* __restrict__ po,
    __half* __restrict__ wh, __half* __restrict__ wl,
    __half* __restrict__ xh, __half* __restrict__ xl)
{
    int idx = blockIdx.x * 256 + threadIdx.x;
    switch (blockIdx.y) {
    case 0: prep_one(cinw, wh + OW_CIN, wl + OW_CIN, (int)WSZ_CIN, HH, 80, 1, idx); break;
    case 1: prep_one(e1, wh + OW_E1, wl + OW_E1, (int)WSZ_E1, HH2, HH, 3, idx); break;
    case 2: prep_one(e2, wh + OW_E2, wl + OW_E2, (int)WSZ_E2, HH, HH2, 1, idx); break;
    case 3: prep_one(ep, wh + OW_EP, wl + OW_EP, (int)WSZ_EP, HH, HH, 3, idx); break;
    case 4: prep_one(p1, wh + OW_P1, wl + OW_P1, (int)WSZ_E1, HH2, HH, 3, idx); break;
    case 5: prep_one(p2, wh + OW_P2, wl + OW_P2, (int)WSZ_E2, HH, HH2, 1, idx); break;
    case 6: prep_one(pp, wh + OW_PP, wl + OW_PP, (int)WSZ_EP, HH, HH, 3, idx); break;
    case 7: prep_one(pi, wh + OW_PI, wl + OW_PI, (int)WSZ_PI, CVQd, HH, 1, idx); break;
    case 8: prep_one(po, wh + OW_PO, wl + OW_PO, (int)WSZ_PO, HH, CVQd, 1, idx); break;
    default:
        if (idx < (int)SZ_X) {
            int b = idx / (80 * TT);
            int r = idx - b * 80 * TT;
            int c = r / TT, t = r - c * TT;
            __half h, l;
            split_f16(x[idx], h, l);
            size_t o = ((size_t)b * TT + t) * 80 + c;
            xh[o] = h; xl[o] = l;
        }
        break;
    }
}

// ---------------- LayerNorm (t-major): warp per row ----------------
__global__ void ln_kernel(const float* __restrict__ in, __half* __restrict__ outh,
                          __half* __restrict__ outl,
                          const float* __restrict__ gma, const float* __restrict__ bta,
                          const float* __restrict__ mask, int Tdim)
{
    int row = blockIdx.x * 8 + (threadIdx.x >> 5);
    if (row >= BB * Tdim) return;
    int lane = threadIdx.x & 31;
    const float4* p = (const float4*)(in + (size_t)row * HH) + lane * 2;
    float4 a = p[0], q = p[1];
    float v[8] = {a.x, a.y, a.z, a.w, q.x, q.y, q.z, q.w};
    float s = 0.f, s2 = 0.f;
    #pragma unroll
    for (int i = 0; i < 8; i++) { s += v[i]; s2 += v[i] * v[i]; }
    #pragma unroll
    for (int o = 16; o; o >>= 1) {
        s  += __shfl_xor_sync(0xffffffffu, s, o);
        s2 += __shfl_xor_sync(0xffffffffu, s2, o);
    }
    float mean = s * (1.f / HH);
    float var  = s2 * (1.f / HH) - mean * mean;
    float r = rsqrtf(var + 1e-5f);
    float mk = mask ? mask[row] : 1.f;
    __half2 hv[4], lv[4];
    #pragma unroll
    for (int i = 0; i < 4; i++) {
        int c = lane * 8 + 2 * i;
        float n0 = ((v[2*i]   - mean) * r * gma[c]     + bta[c])     * mk;
        float n1 = ((v[2*i+1] - mean) * r * gma[c + 1] + bta[c + 1]) * mk;
        __half h0, l0, h1, l1;
        split_f16(n0, h0, l0);
        split_f16(n1, h1, l1);
        hv[i] = __halves2half2(h0, h1);
        lv[i] = __halves2half2(l0, l1);
    }
    *(uint4*)(outh + (size_t)row * HH + lane * 8) = *(uint4*)hv;
    *(uint4*)(outl + (size_t)row * HH + lane * 8) = *(uint4*)lv;
}

// ---------------- fp16-split mma.sync conv GEMM ----------------
// 3-buffer cp.async pipeline, ONE __syncthreads per stage.
// KS=3: X stored un-replicated as 130 rows [tg-2, tg+128) x 16ci; taps = ldmatrix row shifts.
// KS=1: stage = 32 ci (2 k16-steps).
template<int KS>
__global__ void __launch_bounds__(256)
mma_conv(const __half* __restrict__ inh, const __half* __restrict__ inl,
         const __half* __restrict__ wh, const __half* __restrict__ wl,
         const float* __restrict__ bias,
         float* outF, int tmaj, __half* outH, __half* outL,
         const float* __restrict__ residual, const float* __restrict__ mask,
         int Cin, int Cout, int Tdim, float scale, int dogelu)
{
    extern __shared__ char smc[];
    // halves per plane / buffer
    constexpr int XPL = (KS == 3) ? 3168 : 5120;   // KS3: 132rows x 24 ; KS1: 128 x 40
    constexpr int WPL = (KS == 3) ? 3584 : 2560;   // KS3: 64 x 56 ; KS1: 64 x 40
    constexpr int BUF = 2 * (XPL + WPL);
    constexpr int SXW = (KS == 3) ? 56 : 40;       // W row stride (halves)
    constexpr int SXX = (KS == 3) ? 24 : 40;       // X row stride (halves)

    const int b   = blockIdx.z;
    const int cog = blockIdx.y * 64;
    const int tg  = blockIdx.x * 128;
    const int tid = threadIdx.x;
    const int lane = tid & 31, wid = tid >> 5;
    const int wm = wid >> 2, wn = wid & 3;
    const int g = lane >> 2, th = lane & 3;

    const uint32_t smb = smem_to_u32(smc);
    const int Ktot = Cin * KS;
    const size_t xb = (size_t)b * Tdim * Cin;   // half units

    const int laneA = ((lane & 7) + ((lane >> 3) & 1) * 8) * SXW + (lane >> 4) * 8;
    const int laneB = ((lane & 7) + (lane >> 4) * 8) * SXX + ((lane >> 3) & 1) * 8;

    float c[2][4][4];
    #pragma unroll
    for (int i = 0; i < 2; i++)
        #pragma unroll
        for (int j = 0; j < 4; j++)
            #pragma unroll
            for (int k = 0; k < 4; k++) c[i][j][k] = 0.f;

    const int nst = (KS == 3) ? (Cin >> 4) : ((Cin + 31) >> 5);

    auto load_stage = [&](int s, int buf) {
        const uint32_t bb = smb + 2u * (uint32_t)(buf * BUF);
        if (KS == 3) {
            const int ci0 = s * 16;
            // W: 2 planes x 64 rows x 6 chunks = 768
            for (int ic = tid; ic < 768; ic += 256) {
                int plane = ic / 384, r = ic - plane * 384;
                int row = r / 6, ch = r - row * 6;
                const __half* src = (plane ? wl : wh) + (size_t)(cog + row) * Ktot + s * 48 + ch * 8;
                CP16(bb + 2u * (uint32_t)(2 * XPL + plane * WPL + row * SXW + ch * 8), src);
            }
            // X: 2 planes x 130 rows x 2 chunks = 520
            for (int ic = tid; ic < 520; ic += 256) {
                int plane = ic / 260, r = ic - plane * 260;
                int u = r >> 1, ch = r & 1;
                int gt = tg - 2 + u;
                const __half* src = (plane ? inl : inh) + xb + (size_t)gt * Cin + ci0 + ch * 8;
                int ssz = (gt >= 0) ? 16 : 0;
                CP16Z(bb + 2u * (uint32_t)(plane * XPL + u * SXX + ch * 8), src, ssz);
            }
        } else {
            const int ci0 = s * 32;
            const int steps = ((Cin - ci0) >= 32) ? 2 : 1;
            const int cw = steps * 2;
            for (int ic = tid; ic < 2 * 64 * cw; ic += 256) {
                int plane = ic / (64 * cw), r = ic - plane * (64 * cw);
                int row = r / cw, ch = r - row * cw;
                const __half* src = (plane ? wl : wh) + (size_t)(cog + row) * Ktot + ci0 + ch * 8;
                CP16(bb + 2u * (uint32_t)(2 * XPL + plane * WPL + row * SXW + ch * 8), src);
            }
            for (int ic = tid; ic < 2 * 128 * cw; ic += 256) {
                int plane = ic / (128 * cw), r = ic - plane * (128 * cw);
                int t = r / cw, ch = r - t * cw;
                const __half* src = (plane ? inl : inh) + xb + (size_t)(tg + t) * Cin + ci0 + ch * 8;
                CP16(bb + 2u * (uint32_t)(plane * XPL + t * SXX + ch * 8), src);
            }
        }
    };

    auto compute = [&](int buf, int ksteps) {
        const uint32_t bb = smb + 2u * (uint32_t)(buf * BUF);
        for (int ks = 0; ks < ksteps; ks++) {
            uint32_t ah[2][4], al[2][4], bh[4][2], bl[4][2];
            #pragma unroll
            for (int mf = 0; mf < 2; mf++) {
                uint32_t base = bb + 2u * (uint32_t)(2 * XPL + (wm * 32 + mf * 16) * SXW + ks * 16 + laneA);
                LDSM4(ah[mf][0], ah[mf][1], ah[mf][2], ah[mf][3], base);
                LDSM4(al[mf][0], al[mf][1], al[mf][2], al[mf][3], base + 2u * (uint32_t)WPL);
            }
            #pragma unroll
            for (int p = 0; p < 2; p++) {
                // KS=3: tap 'ks' selects X rows shifted by ks (row u = t_local + ks)
                int rowb = wn * 32 + p * 16 + ((KS == 3) ? ks : 0);
                int colb = (KS == 3) ? 0 : ks * 16;
                uint32_t base = bb + 2u * (uint32_t)(rowb * SXX + colb + laneB);
                LDSM4(bh[2*p][0], bh[2*p][1], bh[2*p+1][0], bh[2*p+1][1], base);
                LDSM4(bl[2*p][0], bl[2*p][1], bl[2*p+1][0], bl[2*p+1][1], base + 2u * (uint32_t)XPL);
            }
            #pragma unroll
            for (int mf = 0; mf < 2; mf++)
                #pragma unroll
                for (int nf = 0; nf < 4; nf++) {
                    MMA_F16(c[mf][nf], ah[mf], bh[nf]);
                    MMA_F16(c[mf][nf], ah[mf], bl[nf]);
                    MMA_F16(c[mf][nf], al[mf], bh[nf]);
                }
        }
    };

    // ---- 3-buffer pipeline, 1 sync per stage ----
    load_stage(0, 0);
    asm volatile("cp.async.commit_group;");
    if (nst > 1) load_stage(1, 1);
    asm volatile("cp.async.commit_group;");
    for (int s = 0; s < nst; s++) {
        asm volatile("cp.async.wait_group 1;");
        __syncthreads();
        if (s + 2 < nst) load_stage(s + 2, (s + 2) % 3);
        asm volatile("cp.async.commit_group;");
        int ksteps = (KS == 3) ? 3 : (((Cin - s * 32) >= 32) ? 2 : 1);
        compute(s % 3, ksteps);
    }

    // ---- epilogue ----
    #pragma unroll
    for (int mf = 0; mf < 2; mf++) {
        #pragma unroll
        for (int nf = 0; nf < 4; nf++) {
            int co0 = cog + wm * 32 + mf * 16 + g;
            int t0 = tg + wn * 32 + nf * 8 + 2 * th;
            float mk0 = mask ? mask[b * Tdim + t0] : 1.f;
            float mk1 = mask ? mask[b * Tdim + t0 + 1] : 1.f;
            #pragma unroll
            for (int half = 0; half < 2; half++) {
                int co = co0 + half * 8;
                float bi = bias[co];
                float v0 = (c[mf][nf][half * 2 + 0] + bi) * scale;
                float v1 = (c[mf][nf][half * 2 + 1] + bi) * scale;
                if (dogelu) {
                    v0 = 0.5f * v0 * (1.f + erff(v0 * 0.70710678118654752f));
                    v1 = 0.5f * v1 * (1.f + erff(v1 * 0.70710678118654752f));
                }
                size_t r0 = ((size_t)b * Tdim + t0) * Cout + co;
                size_t r1 = r0 + Cout;
                if (residual) { v0 += residual[r0]; v1 += residual[r1]; }
                if (mask) { v0 *= mk0; v1 *= mk1; }
                if (outF) {
                    if (tmaj) { outF[r0] = v0; outF[r1] = v1; }
                    else {
                        size_t o = ((size_t)b * Cout + co) * Tdim + t0;
                        outF[o] = v0; outF[o + 1] = v1;
                    }
                }
                if (outH) {
                    __half h0, l0, h1, l1;
                    split_f16(v0, h0, l0);
                    split_f16(v1, h1, l1);
                    outH[r0] = h0; outH[r1] = h1;
                    outL[r0] = l0; outL[r1] = l1;
                }
            }
        }
    }
}

// ---------------- group_by_segs (t-major) ----------------
__global__ void seg_zero(float* seg, float* cnt)
{
    int i = blockIdx.x * blockDim.x + threadIdx.x;
    if (i < (int)SZ_SEG) seg[i] = 0.f;
    if (i < (int)SZ_CNT) cnt[i] = 0.f;
}
__global__ void seg_scatter(const float* __restrict__ in, const int* __restrict__ mel2ph,
                            float* seg, float* cnt)
{
    int t = blockIdx.x, b = blockIdx.y, c = threadIdx.x;
    int ph = mel2ph[b * TT + t];
    if (ph < 1 || ph > LL) return;
    float v = in[((size_t)b * TT + t) * HH + c];
    atomicAdd(&seg[((size_t)b * (LL + 1) + ph) * HH + c], v);
    if (c == 0) atomicAdd(&cnt[b * (LL + 1) + ph], 1.f);
}
__global__ void seg_div(const float* __restrict__ seg, const float* __restrict__ cnt,
                        float* __restrict__ outg)
{
    int i = blockIdx.x * blockDim.x + threadIdx.x;   // over [b][l][c]
    if (i >= BB * LL * HH) return;
    int c = i % HH; int bl = i / HH; int l = bl % LL; int b = bl / LL;
    float s = seg[((size_t)b * (LL + 1) + l + 1) * HH + c];
    float n = fmaxf(cnt[b * (LL + 1) + l + 1], 1.f);
    outg[i] = s / n;
}

// ---------------- VQ (t-major) ----------------
__global__ void loss_init(float* loss) { if (threadIdx.x == 0) *loss = 0.f; }

__global__ void vq_kernel(const float* __restrict__ z, const float* __restrict__ cb,
                          __half* __restrict__ qh, __half* __restrict__ ql,
                          float* __restrict__ outIdx, float* loss)
{
    __shared__ float zsh[64];
    __shared__ float dsh[128];
    __shared__ int   ish[128];
    int l = blockIdx.x, b = blockIdx.y, tid = threadIdx.x;
    if (tid < 64) zsh[tid] = z[((size_t)b * LL + l) * CVQd + tid];
    __syncthreads();
    float x2 = 0.f, dot = 0.f, c2 = 0.f;
    #pragma unroll 8
    for (int c = 0; c < 64; c++) {
        float zv = zsh[c]; float cv = cb[tid * 64 + c];
        x2 += zv * zv; dot += zv * cv; c2 += cv * cv;
    }
    dsh[tid] = x2 - 2.f * dot + c2;
    ish[tid] = tid;
    __syncthreads();
    for (int s = 64; s > 0; s >>= 1) {
        if (tid < s) {
            float d2 = dsh[tid + s]; int i2 = ish[tid + s];
            if (d2 < dsh[tid] || (d2 == dsh[tid] && i2 < ish[tid])) { dsh[tid] = d2; ish[tid] = i2; }
        }
        __syncthreads();
    }
    int best = ish[0];
    __syncthreads();
    float part = 0.f;
    if (tid < 64) {
        float qv = cb[best * 64 + tid];
        size_t oi = ((size_t)b * LL + l) * CVQd + tid;
        __half h, lo;
        split_f16(qv, h, lo);
        qh[oi] = h; ql[oi] = lo;
        float dd = zsh[tid] - qv;
        part = dd * dd;
    }
    dsh[tid] = part;
    __syncthreads();
    for (int s = 64; s > 0; s >>= 1) { if (tid < s) dsh[tid] += dsh[tid + s]; __syncthreads(); }
    if (tid == 0) {
        atomicAdd(loss, dsh[0]);
        outIdx[b * LL + l] = (float)best;
    }
}

__global__ void loss_fin(const float* loss, float* out)
{
    out[0] = loss[0] * 0.25f / (float)(BB * LL * CVQd);
}

// ---------------- launch ----------------
extern "C" void kernel_launch(void* const* d_in, const int* in_sizes, int n_in,
                              void* d_out, int out_size)
{
    float* scratch = nullptr;
    cudaGetSymbolAddress((void**)&scratch, g_scratch);
    float*  bx  = scratch + O_BX;
    float*  by  = scratch + O_BY;
    __half* bnh = (__half*)(scratch + O_BNH);
    __half* bnl = (__half*)(scratch + O_BNL);
    __half* bmh = (__half*)(scratch + O_BMH);
    __half* bml = (__half*)(scratch + O_BML);
    __half* xh  = (__half*)(scratch + O_XH);
    __half* xl  = (__half*)(scratch + O_XL);
    __half* byh = (__half*)(scratch + O_BYH);
    __half* byl = (__half*)(scratch + O_BYL);
    float*  seg = scratch + O_SEG;
    float*  cnt = scratch + O_CNT;
    float*  bz  = scratch + O_BZ;
    __half* qh  = (__half*)(scratch + O_QH);
    __half* ql  = (__half*)(scratch + O_QL);
    float*  loss = scratch + O_LOSS;
    __half* wh  = (__half*)(scratch + O_WH);
    __half* wl  = (__half*)(scratch + O_WL);

    const float* x        = (const float*)d_in[0];
    const float* in_mask  = (const float*)d_in[1];
    const int*   mel2ph   = (const int*)  d_in[2];
    const float* ph_mask  = (const float*)d_in[3];
    const float* conv_in_w = (const float*)d_in[4];
    const float* conv_in_b = (const float*)d_in[5];
    const float* enc_ln_g = (const float*)d_in[6];
    const float* enc_ln_b = (const float*)d_in[7];
    const float* enc_w1   = (const float*)d_in[8];
    const float* enc_b1   = (const float*)d_in[9];
    const float* enc_w2   = (const float*)d_in[10];
    const float* enc_b2   = (const float*)d_in[11];
    const float* enc_last_g = (const float*)d_in[12];
    const float* enc_last_b = (const float*)d_in[13];
    const float* enc_post_w = (const float*)d_in[14];
    const float* enc_post_b = (const float*)d_in[15];
    const float* pn_ln_g = (const float*)d_in[16];
    const float* pn_ln_b = (const float*)d_in[17];
    const float* pn_w1   = (const float*)d_in[18];
    const float* pn_b1   = (const float*)d_in[19];
    const float* pn_w2   = (const float*)d_in[20];
    const float* pn_b2   = (const float*)d_in[21];
    const float* pn_last_g = (const float*)d_in[22];
    const float* pn_last_b = (const float*)d_in[23];
    const float* pn_post_w = (const float*)d_in[24];
    const float* pn_post_b = (const float*)d_in[25];
    const float* proj_in_w  = (const float*)d_in[26];
    const float* proj_in_b  = (const float*)d_in[27];
    const float* proj_out_w = (const float*)d_in[28];
    const float* proj_out_b = (const float*)d_in[29];
    const float* codebook   = (const float*)d_in[30];

    float* out = (float*)d_out;
    const float scale = 0.57735026918962576f;   // 3^-0.5

    // smem: KS=3: 3 buf * 2*(3168+3584) halves * 2B = 81024 B
    //       KS=1: 3 buf * 2*(5120+2560) halves * 2B = 92160 B
    const int SM3 = 3 * 2 * (3168 + 3584) * 2;
    const int SM1 = 3 * 2 * (5120 + 2560) * 2;
    cudaFuncSetAttribute(mma_conv<3>, cudaFuncAttributeMaxDynamicSharedMemorySize, SM3);
    cudaFuncSetAttribute(mma_conv<1>, cudaFuncAttributeMaxDynamicSharedMemorySize, SM1);

    dim3 blk(256);

    // ---- prepass (single launch) + early independent zero/init ----
    prep_all<<<dim3(15360, 10), 256>>>(x, conv_in_w, enc_w1, enc_w2, enc_post_w,
                                       pn_w1, pn_w2, pn_post_w, proj_in_w, proj_out_w,
                                       wh, wl, xh, xl);
    seg_zero<<<((int)SZ_SEG + 255)/256, 256>>>(seg, cnt);
    loss_init<<<1, 32>>>(loss);

    // ---- encoder (T = TT) ----
    mma_conv<1><<<dim3(TT/128, HH/64, BB), blk, SM1>>>(xh, xl, wh + OW_CIN, wl + OW_CIN,
        conv_in_b, bx, 1, nullptr, nullptr, nullptr, in_mask, 80, HH, TT, 1.f, 0);
    for (int i = 0; i < NLB; i++) {
        ln_kernel<<<(BB*TT)/8, 256>>>(bx, bnh, bnl,
            enc_ln_g + i*HH, enc_ln_b + i*HH, nullptr, TT);
        mma_conv<3><<<dim3(TT/128, HH2/64, BB), blk, SM3>>>(bnh, bnl,
            wh + OW_E1 + (size_t)i*HH2*HH*3, wl + OW_E1 + (size_t)i*HH2*HH*3,
            enc_b1 + i*HH2, nullptr, 0, bmh, bml, nullptr, nullptr, HH, HH2, TT, scale, 1);
        mma_conv<1><<<dim3(TT/128, HH/64, BB), blk, SM1>>>(bmh, bml,
            wh + OW_E2 + (size_t)i*HH*HH2, wl + OW_E2 + (size_t)i*HH*HH2,
            enc_b2 + i*HH, bx, 1, nullptr, nullptr, bx, in_mask, HH2, HH, TT, 1.f, 0);
    }
    ln_kernel<<<(BB*TT)/8, 256>>>(bx, bnh, bnl, enc_last_g, enc_last_b, in_mask, TT);
    mma_conv<3><<<dim3(TT/128, HH/64, BB), blk, SM3>>>(bnh, bnl, wh + OW_EP, wl + OW_EP,
        enc_post_b, by, 1, nullptr, nullptr, nullptr, in_mask, HH, HH, TT, 1.f, 0);

    // ---- group by segments -> [b][l][c] into bx ----
    seg_scatter<<<dim3(TT, BB), HH>>>(by, mel2ph, seg, cnt);
    seg_div<<<(BB*LL*HH + 255)/256, 256>>>(seg, cnt, bx);

    // ---- postnet (T = LL) ----
    for (int i = 0; i < NLB; i++) {
        ln_kernel<<<(BB*LL)/8, 256>>>(bx, bnh, bnl,
            pn_ln_g + i*HH, pn_ln_b + i*HH, nullptr, LL);
        mma_conv<3><<<dim3(LL/128, HH2/64, BB), blk, SM3>>>(bnh, bnl,
            wh + OW_P1 + (size_t)i*HH2*HH*3, wl + OW_P1 + (size_t)i*HH2*HH*3,
            pn_b1 + i*HH2, nullptr, 0, bmh, bml, nullptr, nullptr, HH, HH2, LL, scale, 1);
        mma_conv<1><<<dim3(LL/128, HH/64, BB), blk, SM1>>>(bmh, bml,
            wh + OW_P2 + (size_t)i*HH*HH2, wl + OW_P2 + (size_t)i*HH*HH2,
            pn_b2 + i*HH, bx, 1, nullptr, nullptr, bx, ph_mask, HH2, HH, LL, 1.f, 0);
    }
    ln_kernel<<<(BB*LL)/8, 256>>>(bx, bnh, bnl, pn_last_g, pn_last_b, ph_mask, LL);
    mma_conv<3><<<dim3(LL/128, HH/64, BB), blk, SM3>>>(bnh, bnl, wh + OW_PP, wl + OW_PP,
        pn_post_b, nullptr, 0, byh, byl, nullptr, ph_mask, HH, HH, LL, 1.f, 0);

    // ---- proj_in -> VQ -> proj_out ----
    mma_conv<1><<<dim3(LL/128, 1, BB), blk, SM1>>>(byh, byl, wh + OW_PI, wl + OW_PI,
        proj_in_b, bz, 1, nullptr, nullptr, nullptr, nullptr, HH, CVQd, LL, 1.f, 0);
    vq_kernel<<<dim3(LL, BB), 128>>>(bz, codebook, qh, ql, out + (size_t)BB*HH*LL + 1, loss);
    mma_conv<1><<<dim3(LL/128, HH/64, BB), blk, SM1>>>(qh, ql, wh + OW_PO, wl + OW_PO,
        proj_out_b, out, 0, nullptr, nullptr, nullptr, nullptr, CVQd, HH, LL, 1.f, 0);
    loss_fin<<<1, 1>>>(loss, out + (size_t)BB*HH*LL);
}

// round 11
// speedup vs baseline: 3.8844x; 1.0930x over previous
#include <cuda_runtime.h>
#include <cuda_fp16.h>
#include <math.h>
#include <stdint.h>

// ---------------- problem constants ----------------
#define BB   16
#define TT   2048
#define LL   512
#define HH   256
#define HH2  512
#define CVQd 64
#define NLB  10   // NL * NB
#define CINP 96   // conv_in padded channels (80 -> 96)

// ---------------- sizes (floats) ----------------
#define SZ_BHT  ((size_t)BB*HH*TT)
#define SZ_BMT  ((size_t)BB*HH2*TT)
#define SZ_XP   ((size_t)BB*CINP*TT)
#define SZ_BHL  ((size_t)BB*HH*LL)
#define SZ_SEG  ((size_t)BB*HH*(LL+1))
#define SZ_CNT  ((size_t)BB*(LL+1))
#define SZ_BZL  ((size_t)BB*CVQd*LL)

// weight plane sizes (elements)
#define WSZ_CIN ((size_t)HH*CINP)
#define WSZ_E1  ((size_t)NLB*HH2*HH*3)
#define WSZ_E2  ((size_t)NLB*HH*HH2)
#define WSZ_EP  ((size_t)HH*HH*3)
#define WSZ_PI  ((size_t)CVQd*HH)
#define WSZ_PO  ((size_t)HH*CVQd)
#define WTOT    (WSZ_CIN + 2*(WSZ_E1 + WSZ_E2 + WSZ_EP) + WSZ_PI + WSZ_PO)

// scratch offsets (float units). half planes take size/2 floats.
// ALL activation tensors are t-major: [b][t][c].
#define O_BX   ((size_t)0)
#define O_BY   (O_BX  + SZ_BHT)
#define O_BNH  (O_BY  + SZ_BHT)
#define O_BNL  (O_BNH + SZ_BHT/2)
#define O_BMH  (O_BNL + SZ_BHT/2)
#define O_BML  (O_BMH + SZ_BMT/2)
#define O_XH   (O_BML + SZ_BMT/2)
#define O_XL   (O_XH  + SZ_XP/2)
#define O_BYH  (O_XL  + SZ_XP/2)
#define O_BYL  (O_BYH + SZ_BHL/2)
#define O_SEG  (O_BYL + SZ_BHL/2)
#define O_CNT  (O_SEG + SZ_SEG)
#define O_BZ   (O_CNT + SZ_CNT)
#define O_QH   (O_BZ  + SZ_BZL)
#define O_QL   (O_QH  + SZ_BZL/2)
#define O_LOSS (O_QL  + SZ_BZL/2)
#define O_WH   (O_LOSS + 16)
#define O_WL   (O_WH  + WTOT/2)
#define SCRATCH_TOT (O_WL + WTOT/2)

__device__ __align__(16) float g_scratch[SCRATCH_TOT];

// weight offsets inside wh/wl planes (element units)
#define OW_CIN ((size_t)0)
#define OW_E1  (OW_CIN + WSZ_CIN)
#define OW_E2  (OW_E1 + WSZ_E1)
#define OW_EP  (OW_E2 + WSZ_E2)
#define OW_P1  (OW_EP + WSZ_EP)
#define OW_P2  (OW_P1 + WSZ_E1)
#define OW_PP  (OW_P2 + WSZ_E2)
#define OW_PI  (OW_PP + WSZ_EP)
#define OW_PO  (OW_PI + WSZ_PI)

// ---------------- helpers ----------------
__device__ __forceinline__ uint32_t smem_to_u32(const void* p) {
    uint32_t a;
    asm("{ .reg .u64 t; cvta.to.shared.u64 t, %1; cvt.u32.u64 %0, t; }" : "=r"(a) : "l"(p));
    return a;
}
#define CP16(dst, src) \
    asm volatile("cp.async.cg.shared.global [%0], [%1], 16;" :: "r"(dst), "l"(src))
#define CP16Z(dst, src, ssz) \
    asm volatile("cp.async.cg.shared.global [%0], [%1], 16, %2;" :: "r"(dst), "l"(src), "r"(ssz))

#define LDSM4(r0, r1, r2, r3, addr)                                              \
    asm volatile("ldmatrix.sync.aligned.m8n8.x4.shared.b16 {%0,%1,%2,%3}, [%4];" \
        : "=r"(r0), "=r"(r1), "=r"(r2), "=r"(r3) : "r"(addr))

#define MMA_F16(C, A, B)                                                         \
    asm volatile("mma.sync.aligned.m16n8k16.row.col.f32.f16.f16.f32 "            \
        "{%0,%1,%2,%3}, {%4,%5,%6,%7}, {%8,%9}, {%0,%1,%2,%3};"                  \
        : "+f"((C)[0]), "+f"((C)[1]), "+f"((C)[2]), "+f"((C)[3])                  \
        : "r"((A)[0]), "r"((A)[1]), "r"((A)[2]), "r"((A)[3]),                     \
          "r"((B)[0]), "r"((B)[1]))

__device__ __forceinline__ void split_f16(float v, __half& h, __half& l)
{
    h = __float2half_rn(v);
    l = __float2half_rn(v - __half2float(h));
}

// ---------------- merged prepass ----------------
__device__ __forceinline__ void prep_one(const float* __restrict__ w,
                                         __half* __restrict__ oh, __half* __restrict__ ol,
                                         int total, int Cout, int Cin, int KS, int idx)
{
    if (idx >= total) return;
    int per_layer = Cout * Cin * KS;
    int layer = idx / per_layer;
    int r = idx - layer * per_layer;
    int co = r / (Cin * KS);
    int r2 = r - co * (Cin * KS);
    int ci = r2 / KS;
    int tap = r2 - ci * KS;
    __half h, l;
    split_f16(w[idx], h, l);
    int kidx = (ci >> 4) * (16 * KS) + tap * 16 + (ci & 15);
    size_t o = ((size_t)layer * Cout + co) * (size_t)(Cin * KS) + kidx;
    oh[o] = h; ol[o] = l;
}

__global__ void prep_all(
    const float* __restrict__ x,
    const float* __restrict__ cinw, const float* __restrict__ e1,
    const float* __restrict__ e2,  const float* __restrict__ ep,
    const float* __restrict__ p1,  const float* __restrict__ p2,
    const float* __restrict__ pp,  const float* __restrict__ pi,
    const float* __restrict__ po,
    __half* __restrict__ wh, __half* __restrict__ wl,
    __half* __restrict__ xh, __half* __restrict__ xl)
{
    int idx = blockIdx.x * 256 + threadIdx.x;
    switch (blockIdx.y) {
    case 0:  // conv_in weights padded 80 -> 96 ci (KS=1, kidx = ci)
        if (idx < (int)WSZ_CIN) {
            int co = idx / CINP, ci = idx - co * CINP;
            float v = (ci < 80) ? cinw[co * 80 + ci] : 0.f;
            __half h, l;
            split_f16(v, h, l);
            wh[OW_CIN + idx] = h; wl[OW_CIN + idx] = l;
        }
        break;
    case 1: prep_one(e1, wh + OW_E1, wl + OW_E1, (int)WSZ_E1, HH2, HH, 3, idx); break;
    case 2: prep_one(e2, wh + OW_E2, wl + OW_E2, (int)WSZ_E2, HH, HH2, 1, idx); break;
    case 3: prep_one(ep, wh + OW_EP, wl + OW_EP, (int)WSZ_EP, HH, HH, 3, idx); break;
    case 4: prep_one(p1, wh + OW_P1, wl + OW_P1, (int)WSZ_E1, HH2, HH, 3, idx); break;
    case 5: prep_one(p2, wh + OW_P2, wl + OW_P2, (int)WSZ_E2, HH, HH2, 1, idx); break;
    case 6: prep_one(pp, wh + OW_PP, wl + OW_PP, (int)WSZ_EP, HH, HH, 3, idx); break;
    case 7: prep_one(pi, wh + OW_PI, wl + OW_PI, (int)WSZ_PI, CVQd, HH, 1, idx); break;
    case 8: prep_one(po, wh + OW_PO, wl + OW_PO, (int)WSZ_PO, HH, CVQd, 1, idx); break;
    default:  // x -> 96-channel t-major planes (zero-padded)
        if (idx < (int)SZ_XP) {
            int b = idx / (CINP * TT);
            int r = idx - b * CINP * TT;
            int t = r / CINP, c = r - t * CINP;
            float v = (c < 80) ? x[((size_t)b * 80 + c) * TT + t] : 0.f;
            __half h, l;
            split_f16(v, h, l);
            size_t o = ((size_t)b * TT + t) * CINP + c;
            xh[o] = h; xl[o] = l;
        }
        break;
    }
}

// ---------------- LayerNorm (t-major): warp per row ----------------
__global__ void ln_kernel(const float* __restrict__ in, __half* __restrict__ outh,
                          __half* __restrict__ outl,
                          const float* __restrict__ gma, const float* __restrict__ bta,
                          const float* __restrict__ mask, int Tdim)
{
    int row = blockIdx.x * 8 + (threadIdx.x >> 5);
    if (row >= BB * Tdim) return;
    int lane = threadIdx.x & 31;
    const float4* p = (const float4*)(in + (size_t)row * HH) + lane * 2;
    float4 a = p[0], q = p[1];
    float v[8] = {a.x, a.y, a.z, a.w, q.x, q.y, q.z, q.w};
    float s = 0.f, s2 = 0.f;
    #pragma unroll
    for (int i = 0; i < 8; i++) { s += v[i]; s2 += v[i] * v[i]; }
    #pragma unroll
    for (int o = 16; o; o >>= 1) {
        s  += __shfl_xor_sync(0xffffffffu, s, o);
        s2 += __shfl_xor_sync(0xffffffffu, s2, o);
    }
    float mean = s * (1.f / HH);
    float var  = s2 * (1.f / HH) - mean * mean;
    float r = rsqrtf(var + 1e-5f);
    float mk = mask ? mask[row] : 1.f;
    __half2 hv[4], lv[4];
    #pragma unroll
    for (int i = 0; i < 4; i++) {
        int c = lane * 8 + 2 * i;
        float n0 = ((v[2*i]   - mean) * r * gma[c]     + bta[c])     * mk;
        float n1 = ((v[2*i+1] - mean) * r * gma[c + 1] + bta[c + 1]) * mk;
        __half h0, l0, h1, l1;
        split_f16(n0, h0, l0);
        split_f16(n1, h1, l1);
        hv[i] = __halves2half2(h0, h1);
        lv[i] = __halves2half2(l0, l1);
    }
    *(uint4*)(outh + (size_t)row * HH + lane * 8) = *(uint4*)hv;
    *(uint4*)(outl + (size_t)row * HH + lane * 8) = *(uint4*)lv;
}

// ---------------- fp16-split mma.sync conv GEMM ----------------
// KS=3: 4-buffer pipeline (prefetch distance 3, wait_group 2), stage = 16 ci,
//       X un-replicated 130 rows x 16ci (48B rows); taps = ldmatrix row shifts.
// KS=1: 3-buffer pipeline (distance 2, wait_group 1), stage = 32 ci, 80B rows.
template<int KS>
__global__ void __launch_bounds__(256, 2)
mma_conv(const __half* __restrict__ inh, const __half* __restrict__ inl,
         const __half* __restrict__ wh, const __half* __restrict__ wl,
         const float* __restrict__ bias,
         float* outF, int tmaj, __half* outH, __half* outL,
         const float* __restrict__ residual, const float* __restrict__ mask,
         int Cin, int Cout, int Tdim, float scale, int dogelu)
{
    extern __shared__ char smc[];
    constexpr int SXX = (KS == 3) ? 24 : 40;       // X row stride (halves); bytes mult of 16
    constexpr int SXW = (KS == 3) ? 56 : 40;       // W row stride (halves)
    constexpr int XPL = (KS == 3) ? 132 * 24 : 128 * 40;
    constexpr int WPL = 64 * SXW;
    constexpr int BUF = 2 * (XPL + WPL);
    constexpr int NBUF = (KS == 3) ? 4 : 3;

    const int b   = blockIdx.z;
    const int cog = blockIdx.y * 64;
    const int tg  = blockIdx.x * 128;
    const int tid = threadIdx.x;
    const int lane = tid & 31, wid = tid >> 5;
    const int wm = wid >> 2, wn = wid & 3;
    const int g = lane >> 2, th = lane & 3;

    const uint32_t smb = smem_to_u32(smc);
    const int Ktot = Cin * KS;
    const size_t xb = (size_t)b * Tdim * Cin;   // half units

    const int laneA = ((lane & 7) + ((lane >> 3) & 1) * 8) * SXW + (lane >> 4) * 8;
    const int laneB = ((lane & 7) + (lane >> 4) * 8) * SXX + ((lane >> 3) & 1) * 8;

    float c[2][4][4];
    #pragma unroll
    for (int i = 0; i < 2; i++)
        #pragma unroll
        for (int j = 0; j < 4; j++)
            #pragma unroll
            for (int k = 0; k < 4; k++) c[i][j][k] = 0.f;

    const int nst = (KS == 3) ? (Cin >> 4) : (Cin >> 5);

    auto load_stage = [&](int s, int buf) {
        const uint32_t bb = smb + 2u * (uint32_t)(buf * BUF);
        if (KS == 3) {
            const int ci0 = s * 16;
            // W: 2 planes x 64 rows x 6 chunks = 768
            #pragma unroll
            for (int it = 0; it < 3; it++) {
                int ic = it * 256 + tid;
                int plane = (ic >= 384) ? 1 : 0;
                int r = ic - plane * 384;
                int row = r / 6, ch = r - row * 6;
                const __half* src = (plane ? wl : wh) + (size_t)(cog + row) * Ktot + s * 48 + ch * 8;
                CP16(bb + 2u * (uint32_t)(2 * XPL + plane * WPL + row * SXW + ch * 8), src);
            }
            // X: 2 planes x 130 rows x 2 chunks = 520
            #pragma unroll
            for (int it = 0; it < 3; it++) {
                int ic = it * 256 + tid;
                if (ic < 520) {
                    int plane = (ic >= 260) ? 1 : 0;
                    int r = ic - plane * 260;
                    int u = r >> 1, ch = r & 1;
                    int gt = tg - 2 + u;
                    const __half* src = (plane ? inl : inh) + xb + (size_t)gt * Cin + ci0 + ch * 8;
                    int ssz = (gt >= 0) ? 16 : 0;
                    CP16Z(bb + 2u * (uint32_t)(plane * XPL + u * SXX + ch * 8), src, ssz);
                }
            }
        } else {
            const int ci0 = s * 32;
            // W: 2 planes x 64 rows x 4 chunks = 512
            #pragma unroll
            for (int it = 0; it < 2; it++) {
                int ic = it * 256 + tid;
                int plane = ic >> 8, r = ic & 255;
                int row = r >> 2, ch = r & 3;
                const __half* src = (plane ? wl : wh) + (size_t)(cog + row) * Ktot + ci0 + ch * 8;
                CP16(bb + 2u * (uint32_t)(2 * XPL + plane * WPL + row * SXW + ch * 8), src);
            }
            // X: 2 planes x 128 rows x 4 chunks = 1024
            #pragma unroll
            for (int it = 0; it < 4; it++) {
                int ic = it * 256 + tid;
                int plane = ic >> 9, r = ic & 511;
                int t = r >> 2, ch = r & 3;
                const __half* src = (plane ? inl : inh) + xb + (size_t)(tg + t) * Cin + ci0 + ch * 8;
                CP16(bb + 2u * (uint32_t)(plane * XPL + t * SXX + ch * 8), src);
            }
        }
    };

    auto compute = [&](int buf) {
        const uint32_t bb = smb + 2u * (uint32_t)(buf * BUF);
        constexpr int KST = (KS == 3) ? 3 : 2;
        #pragma unroll
        for (int ks = 0; ks < KST; ks++) {
            uint32_t ah[2][4], al[2][4], bh[4][2], bl[4][2];
            #pragma unroll
            for (int mf = 0; mf < 2; mf++) {
                uint32_t base = bb + 2u * (uint32_t)(2 * XPL + (wm * 32 + mf * 16) * SXW + ks * 16 + laneA);
                LDSM4(ah[mf][0], ah[mf][1], ah[mf][2], ah[mf][3], base);
                LDSM4(al[mf][0], al[mf][1], al[mf][2], al[mf][3], base + 2u * (uint32_t)WPL);
            }
            #pragma unroll
            for (int p = 0; p < 2; p++) {
                int rowb = wn * 32 + p * 16 + ((KS == 3) ? ks : 0);
                int colb = (KS == 3) ? 0 : ks * 16;
                uint32_t base = bb + 2u * (uint32_t)(rowb * SXX + colb + laneB);
                LDSM4(bh[2*p][0], bh[2*p][1], bh[2*p+1][0], bh[2*p+1][1], base);
                LDSM4(bl[2*p][0], bl[2*p][1], bl[2*p+1][0], bl[2*p+1][1], base + 2u * (uint32_t)XPL);
            }
            #pragma unroll
            for (int mf = 0; mf < 2; mf++)
                #pragma unroll
                for (int nf = 0; nf < 4; nf++) {
                    MMA_F16(c[mf][nf], ah[mf], bh[nf]);
                    MMA_F16(c[mf][nf], ah[mf], bl[nf]);
                    MMA_F16(c[mf][nf], al[mf], bh[nf]);
                }
        }
    };

    // ---- pipelined mainloop (prefetch distance NBUF-1) ----
    {
        int pre = (nst < NBUF - 1) ? nst : (NBUF - 1);
        for (int p = 0; p < pre; p++) {
            load_stage(p, p);
            asm volatile("cp.async.commit_group;");
        }
    }
    for (int s = 0; s < nst; s++) {
        if (KS == 3) {
            if (s + 2 < nst)      asm volatile("cp.async.wait_group 2;");
            else if (s + 1 < nst) asm volatile("cp.async.wait_group 1;");
            else                  asm volatile("cp.async.wait_group 0;");
        } else {
            if (s + 1 < nst)      asm volatile("cp.async.wait_group 1;");
            else                  asm volatile("cp.async.wait_group 0;");
        }
        __syncthreads();
        if (s + NBUF - 1 < nst) {
            load_stage(s + NBUF - 1, (s + NBUF - 1) % NBUF);
            asm volatile("cp.async.commit_group;");
        }
        compute(s % NBUF);
    }

    // ---- epilogue ----
    #pragma unroll
    for (int mf = 0; mf < 2; mf++) {
        #pragma unroll
        for (int nf = 0; nf < 4; nf++) {
            int co0 = cog + wm * 32 + mf * 16 + g;
            int t0 = tg + wn * 32 + nf * 8 + 2 * th;
            float mk0 = mask ? mask[b * Tdim + t0] : 1.f;
            float mk1 = mask ? mask[b * Tdim + t0 + 1] : 1.f;
            #pragma unroll
            for (int half = 0; half < 2; half++) {
                int co = co0 + half * 8;
                float bi = bias[co];
                float v0 = (c[mf][nf][half * 2 + 0] + bi) * scale;
                float v1 = (c[mf][nf][half * 2 + 1] + bi) * scale;
                if (dogelu) {
                    v0 = 0.5f * v0 * (1.f + erff(v0 * 0.70710678118654752f));
                    v1 = 0.5f * v1 * (1.f + erff(v1 * 0.70710678118654752f));
                }
                size_t r0 = ((size_t)b * Tdim + t0) * Cout + co;
                size_t r1 = r0 + Cout;
                if (residual) { v0 += residual[r0]; v1 += residual[r1]; }
                if (mask) { v0 *= mk0; v1 *= mk1; }
                if (outF) {
                    if (tmaj) { outF[r0] = v0; outF[r1] = v1; }
                    else {
                        size_t o = ((size_t)b * Cout + co) * Tdim + t0;
                        outF[o] = v0; outF[o + 1] = v1;
                    }
                }
                if (outH) {
                    __half h0, l0, h1, l1;
                    split_f16(v0, h0, l0);
                    split_f16(v1, h1, l1);
                    outH[r0] = h0; outH[r1] = h1;
                    outL[r0] = l0; outL[r1] = l1;
                }
            }
        }
    }
}

// ---------------- group_by_segs (t-major) ----------------
__global__ void seg_zero(float* seg, float* cnt)
{
    int i = blockIdx.x * blockDim.x + threadIdx.x;
    if (i < (int)SZ_SEG) seg[i] = 0.f;
    if (i < (int)SZ_CNT) cnt[i] = 0.f;
}
__global__ void seg_scatter(const float* __restrict__ in, const int* __restrict__ mel2ph,
                            float* seg, float* cnt)
{
    int t = blockIdx.x, b = blockIdx.y, c = threadIdx.x;
    int ph = mel2ph[b * TT + t];
    if (ph < 1 || ph > LL) return;
    float v = in[((size_t)b * TT + t) * HH + c];
    atomicAdd(&seg[((size_t)b * (LL + 1) + ph) * HH + c], v);
    if (c == 0) atomicAdd(&cnt[b * (LL + 1) + ph], 1.f);
}
__global__ void seg_div(const float* __restrict__ seg, const float* __restrict__ cnt,
                        float* __restrict__ outg)
{
    int i = blockIdx.x * blockDim.x + threadIdx.x;   // over [b][l][c]
    if (i >= BB * LL * HH) return;
    int c = i % HH; int bl = i / HH; int l = bl % LL; int b = bl / LL;
    float s = seg[((size_t)b * (LL + 1) + l + 1) * HH + c];
    float n = fmaxf(cnt[b * (LL + 1) + l + 1], 1.f);
    outg[i] = s / n;
}

// ---------------- VQ (t-major) ----------------
__global__ void loss_init(float* loss) { if (threadIdx.x == 0) *loss = 0.f; }

__global__ void vq_kernel(const float* __restrict__ z, const float* __restrict__ cb,
                          __half* __restrict__ qh, __half* __restrict__ ql,
                          float* __restrict__ outIdx, float* loss)
{
    __shared__ float zsh[64];
    __shared__ float dsh[128];
    __shared__ int   ish[128];
    int l = blockIdx.x, b = blockIdx.y, tid = threadIdx.x;
    if (tid < 64) zsh[tid] = z[((size_t)b * LL + l) * CVQd + tid];
    __syncthreads();
    float x2 = 0.f, dot = 0.f, c2 = 0.f;
    #pragma unroll 8
    for (int c = 0; c < 64; c++) {
        float zv = zsh[c]; float cv = cb[tid * 64 + c];
        x2 += zv * zv; dot += zv * cv; c2 += cv * cv;
    }
    dsh[tid] = x2 - 2.f * dot + c2;
    ish[tid] = tid;
    __syncthreads();
    for (int s = 64; s > 0; s >>= 1) {
        if (tid < s) {
            float d2 = dsh[tid + s]; int i2 = ish[tid + s];
            if (d2 < dsh[tid] || (d2 == dsh[tid] && i2 < ish[tid])) { dsh[tid] = d2; ish[tid] = i2; }
        }
        __syncthreads();
    }
    int best = ish[0];
    __syncthreads();
    float part = 0.f;
    if (tid < 64) {
        float qv = cb[best * 64 + tid];
        size_t oi = ((size_t)b * LL + l) * CVQd + tid;
        __half h, lo;
        split_f16(qv, h, lo);
        qh[oi] = h; ql[oi] = lo;
        float dd = zsh[tid] - qv;
        part = dd * dd;
    }
    dsh[tid] = part;
    __syncthreads();
    for (int s = 64; s > 0; s >>= 1) { if (tid < s) dsh[tid] += dsh[tid + s]; __syncthreads(); }
    if (tid == 0) {
        atomicAdd(loss, dsh[0]);
        outIdx[b * LL + l] = (float)best;
    }
}

__global__ void loss_fin(const float* loss, float* out)
{
    out[0] = loss[0] * 0.25f / (float)(BB * LL * CVQd);
}

// ---------------- launch ----------------
extern "C" void kernel_launch(void* const* d_in, const int* in_sizes, int n_in,
                              void* d_out, int out_size)
{
    float* scratch = nullptr;
    cudaGetSymbolAddress((void**)&scratch, g_scratch);
    float*  bx  = scratch + O_BX;
    float*  by  = scratch + O_BY;
    __half* bnh = (__half*)(scratch + O_BNH);
    __half* bnl = (__half*)(scratch + O_BNL);
    __half* bmh = (__half*)(scratch + O_BMH);
    __half* bml = (__half*)(scratch + O_BML);
    __half* xh  = (__half*)(scratch + O_XH);
    __half* xl  = (__half*)(scratch + O_XL);
    __half* byh = (__half*)(scratch + O_BYH);
    __half* byl = (__half*)(scratch + O_BYL);
    float*  seg = scratch + O_SEG;
    float*  cnt = scratch + O_CNT;
    float*  bz  = scratch + O_BZ;
    __half* qh  = (__half*)(scratch + O_QH);
    __half* ql  = (__half*)(scratch + O_QL);
    float*  loss = scratch + O_LOSS;
    __half* wh  = (__half*)(scratch + O_WH);
    __half* wl  = (__half*)(scratch + O_WL);

    const float* x        = (const float*)d_in[0];
    const float* in_mask  = (const float*)d_in[1];
    const int*   mel2ph   = (const int*)  d_in[2];
    const float* ph_mask  = (const float*)d_in[3];
    const float* conv_in_w = (const float*)d_in[4];
    const float* conv_in_b = (const float*)d_in[5];
    const float* enc_ln_g = (const float*)d_in[6];
    const float* enc_ln_b = (const float*)d_in[7];
    const float* enc_w1   = (const float*)d_in[8];
    const float* enc_b1   = (const float*)d_in[9];
    const float* enc_w2   = (const float*)d_in[10];
    const float* enc_b2   = (const float*)d_in[11];
    const float* enc_last_g = (const float*)d_in[12];
    const float* enc_last_b = (const float*)d_in[13];
    const float* enc_post_w = (const float*)d_in[14];
    const float* enc_post_b = (const float*)d_in[15];
    const float* pn_ln_g = (const float*)d_in[16];
    const float* pn_ln_b = (const float*)d_in[17];
    const float* pn_w1   = (const float*)d_in[18];
    const float* pn_b1   = (const float*)d_in[19];
    const float* pn_w2   = (const float*)d_in[20];
    const float* pn_b2   = (const float*)d_in[21];
    const float* pn_last_g = (const float*)d_in[22];
    const float* pn_last_b = (const float*)d_in[23];
    const float* pn_post_w = (const float*)d_in[24];
    const float* pn_post_b = (const float*)d_in[25];
    const float* proj_in_w  = (const float*)d_in[26];
    const float* proj_in_b  = (const float*)d_in[27];
    const float* proj_out_w = (const float*)d_in[28];
    const float* proj_out_b = (const float*)d_in[29];
    const float* codebook   = (const float*)d_in[30];

    float* out = (float*)d_out;
    const float scale = 0.57735026918962576f;   // 3^-0.5

    // smem: KS=3: 4 buf * 2*(3168+3584) halves * 2B = 108032 B (2 CTAs/SM)
    //       KS=1: 3 buf * 2*(5120+2560) halves * 2B =  92160 B (2 CTAs/SM)
    const int SM3 = 4 * 2 * (132 * 24 + 64 * 56) * 2;
    const int SM1 = 3 * 2 * (128 * 40 + 64 * 40) * 2;
    cudaFuncSetAttribute(mma_conv<3>, cudaFuncAttributeMaxDynamicSharedMemorySize, SM3);
    cudaFuncSetAttribute(mma_conv<1>, cudaFuncAttributeMaxDynamicSharedMemorySize, SM1);

    dim3 blk(256);

    // ---- prepass (single launch) + early independent zero/init ----
    prep_all<<<dim3(15360, 10), 256>>>(x, conv_in_w, enc_w1, enc_w2, enc_post_w,
                                       pn_w1, pn_w2, pn_post_w, proj_in_w, proj_out_w,
                                       wh, wl, xh, xl);
    seg_zero<<<((int)SZ_SEG + 255)/256, 256>>>(seg, cnt);
    loss_init<<<1, 32>>>(loss);

    // ---- encoder (T = TT) ----
    mma_conv<1><<<dim3(TT/128, HH/64, BB), blk, SM1>>>(xh, xl, wh + OW_CIN, wl + OW_CIN,
        conv_in_b, bx, 1, nullptr, nullptr, nullptr, in_mask, CINP, HH, TT, 1.f, 0);
    for (int i = 0; i < NLB; i++) {
        ln_kernel<<<(BB*TT)/8, 256>>>(bx, bnh, bnl,
            enc_ln_g + i*HH, enc_ln_b + i*HH, nullptr, TT);
        mma_conv<3><<<dim3(TT/128, HH2/64, BB), blk, SM3>>>(bnh, bnl,
            wh + OW_E1 + (size_t)i*HH2*HH*3, wl + OW_E1 + (size_t)i*HH2*HH*3,
            enc_b1 + i*HH2, nullptr, 0, bmh, bml, nullptr, nullptr, HH, HH2, TT, scale, 1);
        mma_conv<1><<<dim3(TT/128, HH/64, BB), blk, SM1>>>(bmh, bml,
            wh + OW_E2 + (size_t)i*HH*HH2, wl + OW_E2 + (size_t)i*HH*HH2,
            enc_b2 + i*HH, bx, 1, nullptr, nullptr, bx, in_mask, HH2, HH, TT, 1.f, 0);
    }
    ln_kernel<<<(BB*TT)/8, 256>>>(bx, bnh, bnl, enc_last_g, enc_last_b, in_mask, TT);
    mma_conv<3><<<dim3(TT/128, HH/64, BB), blk, SM3>>>(bnh, bnl, wh + OW_EP, wl + OW_EP,
        enc_post_b, by, 1, nullptr, nullptr, nullptr, in_mask, HH, HH, TT, 1.f, 0);

    // ---- group by segments -> [b][l][c] into bx ----
    seg_scatter<<<dim3(TT, BB), HH>>>(by, mel2ph, seg, cnt);
    seg_div<<<(BB*LL*HH + 255)/256, 256>>>(seg, cnt, bx);

    // ---- postnet (T = LL) ----
    for (int i = 0; i < NLB; i++) {
        ln_kernel<<<(BB*LL)/8, 256>>>(bx, bnh, bnl,
            pn_ln_g + i*HH, pn_ln_b + i*HH, nullptr, LL);
        mma_conv<3><<<dim3(LL/128, HH2/64, BB), blk, SM3>>>(bnh, bnl,
            wh + OW_P1 + (size_t)i*HH2*HH*3, wl + OW_P1 + (size_t)i*HH2*HH*3,
            pn_b1 + i*HH2, nullptr, 0, bmh, bml, nullptr, nullptr, HH, HH2, LL, scale, 1);
        mma_conv<1><<<dim3(LL/128, HH/64, BB), blk, SM1>>>(bmh, bml,
            wh + OW_P2 + (size_t)i*HH*HH2, wl + OW_P2 + (size_t)i*HH*HH2,
            pn_b2 + i*HH, bx, 1, nullptr, nullptr, bx, ph_mask, HH2, HH, LL, 1.f, 0);
    }
    ln_kernel<<<(BB*LL)/8, 256>>>(bx, bnh, bnl, pn_last_g, pn_last_b, ph_mask, LL);
    mma_conv<3><<<dim3(LL/128, HH/64, BB), blk, SM3>>>(bnh, bnl, wh + OW_PP, wl + OW_PP,
        pn_post_b, nullptr, 0, byh, byl, nullptr, ph_mask, HH, HH, LL, 1.f, 0);

    // ---- proj_in -> VQ -> proj_out ----
    mma_conv<1><<<dim3(LL/128, 1, BB), blk, SM1>>>(byh, byl, wh + OW_PI, wl + OW_PI,
        proj_in_b, bz, 1, nullptr, nullptr, nullptr, nullptr, HH, CVQd, LL, 1.f, 0);
    vq_kernel<<<dim3(LL, BB), 128>>>(bz, codebook, qh, ql, out + (size_t)BB*HH*LL + 1, loss);
    mma_conv<1><<<dim3(LL/128, HH/64, BB), blk, SM1>>>(qh, ql, wh + OW_PO, wl + OW_PO,
        proj_out_b, out, 0, nullptr, nullptr, nullptr, nullptr, CVQd, HH, LL, 1.f, 0);
    loss_fin<<<1, 1>>>(loss, out + (size_t)BB*HH*LL);
}